// round 7
// baseline (speedup 1.0000x reference)
#include <cuda_runtime.h>
#include <math.h>
#include <stdint.h>

// ---------------- problem constants ----------------
#define D128 128
#define BGR 64
#define NPG0 1024
#define NMAX (BGR * NPG0)        // 65536
#define EMAX 1048576
#define K1 820                   // ceil(0.8*1024)
#define K2 656                   // ceil(0.8*820)
#define K3 525                   // ceil(0.8*656)

// ---------------- scratch (device globals; no allocations allowed) ----------------
__device__ float  g_mean[NMAX * D128];
__device__ float  g_h[NMAX * D128];
__device__ float  g_poolA[BGR * K1 * D128];
__device__ float  g_poolB[BGR * K2 * D128];
__device__ float  g_score[NMAX];
__device__ int    g_newid[NMAX];
__device__ int    g_orig2cur[NMAX];
__device__ int    g_cur2orig[NMAX];
__device__ int    g_deg[NMAX];
__device__ int    g_cursor[NMAX];
__device__ int    g_rowptr[NMAX + 1];
__device__ int    g_nbr[EMAX];
__device__ int    g_part[64];
__device__ int    g_offs[64];
__device__ float2 g_bsplit[3][256 * D128];   // interleaved {hi,lo} of [Wl;Wr], per layer
__device__ float  g_s[BGR * 256];

__device__ __forceinline__ void tf32_split(float v, uint32_t& hi, uint32_t& lo) {
    asm("cvt.rna.tf32.f32 %0, %1;" : "=r"(hi) : "f"(v));
    float r = v - __uint_as_float(hi);
    asm("cvt.rna.tf32.f32 %0, %1;" : "=r"(lo) : "f"(r));
}

__device__ __forceinline__ void mma_m16n8k8(float* c, const uint32_t* a, const uint32_t* b) {
    asm volatile(
        "mma.sync.aligned.m16n8k8.row.col.f32.tf32.tf32.f32 "
        "{%0,%1,%2,%3}, {%4,%5,%6,%7}, {%8,%9}, {%0,%1,%2,%3};"
        : "+f"(c[0]), "+f"(c[1]), "+f"(c[2]), "+f"(c[3])
        : "r"(a[0]), "r"(a[1]), "r"(a[2]), "r"(a[3]), "r"(b[0]), "r"(b[1]));
}

// ---------------- CSR build (once, on original graph) ----------------
__global__ void k_zero_int(int* p, int n) {
    int i = blockIdx.x * blockDim.x + threadIdx.x;
    if (i < n) p[i] = 0;
}

__global__ void k_count(const int* __restrict__ dst, int E, int* __restrict__ deg) {
    int e = blockIdx.x * blockDim.x + threadIdx.x;
    if (e < E) atomicAdd(&deg[dst[e]], 1);
}

__global__ void k_scan1(const int* __restrict__ deg, int* __restrict__ part) {
    __shared__ int s[1024];
    int t = threadIdx.x;
    s[t] = deg[blockIdx.x * 1024 + t];
    __syncthreads();
    for (int off = 512; off > 0; off >>= 1) {
        if (t < off) s[t] += s[t + off];
        __syncthreads();
    }
    if (t == 0) part[blockIdx.x] = s[0];
}

__global__ void k_scan2(const int* __restrict__ part, int* __restrict__ offs) {
    __shared__ int s[64];
    int t = threadIdx.x;
    int my = part[t];
    s[t] = my;
    __syncthreads();
    for (int off = 1; off < 64; off <<= 1) {
        int v = s[t];
        if (t >= off) v += s[t - off];
        __syncthreads();
        s[t] = v;
        __syncthreads();
    }
    offs[t] = s[t] - my;
}

// block-local scan + offsets; also initializes identity survival maps
__global__ void k_scan3(const int* __restrict__ deg, const int* __restrict__ offs,
                        int* __restrict__ rowptr, int* __restrict__ cursor,
                        int* __restrict__ o2c, int* __restrict__ c2o, int n) {
    __shared__ int s[1024];
    int t = threadIdx.x;
    int i = blockIdx.x * 1024 + t;
    int my = deg[i];
    s[t] = my;
    __syncthreads();
    for (int off = 1; off < 1024; off <<= 1) {
        int v = s[t];
        if (t >= off) v += s[t - off];
        __syncthreads();
        s[t] = v;
        __syncthreads();
    }
    int ex = s[t] - my + offs[blockIdx.x];
    rowptr[i] = ex;
    cursor[i] = ex;
    o2c[i] = i;
    c2o[i] = i;
    if (blockIdx.x == 63 && t == 1023) rowptr[n] = ex + my;
}

__global__ void k_scatter(const int* __restrict__ src, const int* __restrict__ dst, int E,
                          int* __restrict__ cursor, int* __restrict__ nbr) {
    int e = blockIdx.x * blockDim.x + threadIdx.x;
    if (e < E) {
        int p = atomicAdd(&cursor[dst[e]], 1);
        nbr[p] = src[e];
    }
}

// ---------------- mean aggregation ----------------
// Layer 1: identity maps — no indirection, no masks.
__global__ void k_aggregate1(const float* __restrict__ X, const int* __restrict__ rowptr,
                             const int* __restrict__ nbr, float* __restrict__ mean, int n) {
    int w = (blockIdx.x * blockDim.x + threadIdx.x) >> 5;
    int lane = threadIdx.x & 31;
    if (w >= n) return;
    int b = rowptr[w], e = rowptr[w + 1];
    float4 acc = make_float4(0.f, 0.f, 0.f, 0.f);
#pragma unroll 4
    for (int j = b; j < e; j++) {
        float4 v = ((const float4*)(X + (size_t)nbr[j] * D128))[lane];
        acc.x += v.x; acc.y += v.y; acc.z += v.z; acc.w += v.w;
    }
    int d = e - b;
    float inv = 1.0f / (float)(d > 0 ? d : 1);
    acc.x *= inv; acc.y *= inv; acc.z *= inv; acc.w *= inv;
    ((float4*)(mean + (size_t)w * D128))[lane] = acc;
}

// Layers 2/3: original CSR + survival maps; warp-uniform skip of dead neighbors.
__global__ void k_aggregate(const float* __restrict__ X, const int* __restrict__ rowptr,
                            const int* __restrict__ nbr, const int* __restrict__ c2o,
                            const int* __restrict__ o2c, float* __restrict__ mean, int n) {
    int w = (blockIdx.x * blockDim.x + threadIdx.x) >> 5;
    int lane = threadIdx.x & 31;
    if (w >= n) return;
    int o = c2o[w];
    int b = rowptr[o], e = rowptr[o + 1];
    float4 acc = make_float4(0.f, 0.f, 0.f, 0.f);
    int cnt = 0;
    for (int j = b; j < e; j++) {
        int c = o2c[nbr[j]];
        if (c >= 0) {   // warp-uniform branch
            float4 v = ((const float4*)(X + (size_t)c * D128))[lane];
            acc.x += v.x; acc.y += v.y; acc.z += v.z; acc.w += v.w;
            cnt++;
        }
    }
    float inv = 1.0f / (float)(cnt > 0 ? cnt : 1);
    acc.x *= inv; acc.y *= inv; acc.z *= inv; acc.w *= inv;
    ((float4*)(mean + (size_t)w * D128))[lane] = acc;
}

// ---------------- weight pre-split for all 3 layers (one launch) ----------------
__global__ void k_splitB_all(const float* __restrict__ Wl1, const float* __restrict__ Wr1,
                             const float* __restrict__ Wl2, const float* __restrict__ Wr2,
                             const float* __restrict__ Wl3, const float* __restrict__ Wr3,
                             float2* __restrict__ bs) {
    int i = blockIdx.x * blockDim.x + threadIdx.x;   // 3 * 32768
    int l = i >> 15, j = i & 32767;
    const float* Wl = (l == 0) ? Wl1 : (l == 1) ? Wl2 : Wl3;
    const float* Wr = (l == 0) ? Wr1 : (l == 1) ? Wr2 : Wr3;
    float v = (j < 16384) ? Wl[j] : Wr[j - 16384];
    uint32_t hi, lo;
    tf32_split(v, hi, lo);
    bs[i] = make_float2(__uint_as_float(hi), __uint_as_float(lo));
}

// ---------------- tf32 mma GEMM v3: interleaved float2, plain loads ----------------
// CTA 128x128, K=256 in 16 chunks of 16. A split at store; B pre-split interleaved.
#define ACH 16
#define AS2 20     // A row stride in float2
#define BS2 132    // B row stride in float2

__global__ void __launch_bounds__(256, 2)
k_gemm_v3(const float* __restrict__ Am, const float* __restrict__ Ax,
          const float2* __restrict__ Bs, const float* __restrict__ bias,
          float* __restrict__ H, int n) {
    __shared__ float2 A2[128 * AS2];
    __shared__ float2 B2[ACH * BS2];
    int t = threadIdx.x, lane = t & 31, wid = t >> 5;
    int wm = (wid >> 2) * 64;
    int wn = (wid & 3) * 32;
    int m0 = blockIdx.x * 128;

    float c[4][4][4];
#pragma unroll
    for (int i = 0; i < 4; i++)
#pragma unroll
        for (int j = 0; j < 4; j++)
#pragma unroll
            for (int r = 0; r < 4; r++) c[i][j][r] = 0.f;

    int arow = t >> 1, acol0 = (t & 1) * 8;
    int brow = t >> 4, bcol0 = (t & 15) * 8;

    for (int ch = 0; ch < 16; ch++) {
        // A chunk [128 x 16], split at store into interleaved float2
        const float* A = (ch < 8) ? Am + (size_t)m0 * D128 + ch * ACH
                                  : Ax + (size_t)m0 * D128 + (ch - 8) * ACH;
        {
            float4 v0 = *(const float4*)(A + (size_t)arow * D128 + acol0);
            float4 v1 = *(const float4*)(A + (size_t)arow * D128 + acol0 + 4);
            float av[8] = {v0.x, v0.y, v0.z, v0.w, v1.x, v1.y, v1.z, v1.w};
            float2* dst = A2 + arow * AS2 + acol0;
#pragma unroll
            for (int e = 0; e < 8; e++) {
                uint32_t hi, lo;
                tf32_split(av[e], hi, lo);
                dst[e] = make_float2(__uint_as_float(hi), __uint_as_float(lo));
            }
        }
        // B chunk [16 x 128] float2, contiguous copy (4x 16B per thread)
        {
            const float4* src = (const float4*)(Bs + ch * 2048 + brow * 128 + bcol0);
            float4* dst = (float4*)(B2 + brow * BS2 + bcol0);
#pragma unroll
            for (int q = 0; q < 4; q++) dst[q] = src[q];
        }
        __syncthreads();

#pragma unroll
        for (int ks = 0; ks < 2; ks++) {
            uint32_t bh[4][2], blo[4][2];
#pragma unroll
            for (int nf = 0; nf < 4; nf++)
#pragma unroll
                for (int r = 0; r < 2; r++) {
                    float2 b = B2[(ks * 8 + (lane & 3) + 4 * r) * BS2 + wn + nf * 8 + (lane >> 2)];
                    bh[nf][r] = __float_as_uint(b.x);
                    blo[nf][r] = __float_as_uint(b.y);
                }
#pragma unroll
            for (int mf = 0; mf < 4; mf++) {
                uint32_t ah[4], al[4];
#pragma unroll
                for (int r = 0; r < 4; r++) {
                    float2 a = A2[(wm + mf * 16 + (lane >> 2) + 8 * (r & 1)) * AS2
                                  + ks * 8 + (lane & 3) + 4 * (r >> 1)];
                    ah[r] = __float_as_uint(a.x);
                    al[r] = __float_as_uint(a.y);
                }
#pragma unroll
                for (int nf = 0; nf < 4; nf++) {
                    mma_m16n8k8(c[mf][nf], ah, bh[nf]);
                    mma_m16n8k8(c[mf][nf], ah, blo[nf]);
                    mma_m16n8k8(c[mf][nf], al, bh[nf]);
                }
            }
        }
        __syncthreads();
    }

    // epilogue: bias + relu
    int r0 = lane >> 2, cq = (lane & 3) * 2;
#pragma unroll
    for (int mf = 0; mf < 4; mf++) {
        int row = m0 + wm + mf * 16 + r0;
#pragma unroll
        for (int nf = 0; nf < 4; nf++) {
            int col = wn + nf * 8 + cq;
            float b0 = bias[col], b1 = bias[col + 1];
            float2 o0, o1;
            o0.x = fmaxf(c[mf][nf][0] + b0, 0.f);
            o0.y = fmaxf(c[mf][nf][1] + b1, 0.f);
            o1.x = fmaxf(c[mf][nf][2] + b0, 0.f);
            o1.y = fmaxf(c[mf][nf][3] + b1, 0.f);
            *(float2*)(H + (size_t)row * D128 + col) = o0;
            *(float2*)(H + (size_t)(row + 8) * D128 + col) = o1;
        }
    }
}

// score[i] = tanh(h_i . pw / ||pw||), one warp per row
__global__ void k_score(const float* __restrict__ H, const float* __restrict__ pw,
                        float* __restrict__ score, int n) {
    int w = (blockIdx.x * blockDim.x + threadIdx.x) >> 5;
    int lane = threadIdx.x & 31;
    if (w >= n) return;
    float4 h4 = ((const float4*)(H + (size_t)w * D128))[lane];
    float4 w4 = ((const float4*)pw)[lane];
    float dot = h4.x * w4.x + h4.y * w4.y + h4.z * w4.z + h4.w * w4.w;
    float nn = w4.x * w4.x + w4.y * w4.y + w4.z * w4.z + w4.w * w4.w;
#pragma unroll
    for (int off = 16; off > 0; off >>= 1) {
        dot += __shfl_xor_sync(0xFFFFFFFF, dot, off);
        nn  += __shfl_xor_sync(0xFFFFFFFF, nn, off);
    }
    if (lane == 0) score[w] = tanhf(dot / sqrtf(nn));
}

// per-graph bitonic top-K + fused pool write + readout + survival-map compose
__global__ void k_topk(const float* __restrict__ score, const float* __restrict__ H,
                       float* __restrict__ pool, int* __restrict__ newid,
                       float* __restrict__ s_out, int* __restrict__ o2c,
                       int* __restrict__ c2o, int Npg, int K, int round, int do_compose) {
    __shared__ float skey[1024];
    __shared__ int   sidx[1024];
    __shared__ float rmx[8][128];
    __shared__ float rsm[8][128];
    int g = blockIdx.x;
    int t = threadIdx.x;   // 1024 threads
    skey[t] = (t < Npg) ? score[g * Npg + t] : -INFINITY;
    sidx[t] = t;
    __syncthreads();
    for (int k = 2; k <= 1024; k <<= 1) {
        for (int j = k >> 1; j > 0; j >>= 1) {
            int ixj = t ^ j;
            if (ixj > t) {
                bool desc = ((t & k) == 0);
                float a = skey[t], b = skey[ixj];
                bool sw = desc ? (a < b) : (a > b);
                if (sw) {
                    skey[t] = b; skey[ixj] = a;
                    int tmp = sidx[t]; sidx[t] = sidx[ixj]; sidx[ixj] = tmp;
                }
            }
            __syncthreads();
        }
    }
    if (t < Npg) {
        int node = sidx[t];
        newid[g * Npg + node] = (t < K) ? (g * K + t) : -1;
    }
    __syncthreads();
    // compose survival maps (this graph's 1024 original nodes)
    if (do_compose) {
        int o = g * NPG0 + t;
        int c = o2c[o];
        int nc = (c >= 0) ? newid[c] : -1;
        o2c[o] = nc;
        if (nc >= 0) c2o[nc] = o;
    }
    // fused pool write + per-feature max/sum
    int f = t & 127, part = t >> 7;     // 8 parts x 128 features
    float mx = -INFINITY, sm = 0.f;
    for (int r = part; r < K; r += 8) {
        int node = sidx[r];
        float v = H[(size_t)(g * Npg + node) * D128 + f] * skey[r];
        pool[(size_t)(g * K + r) * D128 + f] = v;
        mx = fmaxf(mx, v);
        sm += v;
    }
    rmx[part][f] = mx; rsm[part][f] = sm;
    __syncthreads();
    if (t < 128) {
        float m2 = rmx[0][f], s2 = rsm[0][f];
#pragma unroll
        for (int p = 1; p < 8; p++) {
            m2 = fmaxf(m2, rmx[p][f]);
            s2 += rsm[p][f];
        }
        float mean = s2 / (float)K;
        if (round == 0) {
            s_out[g * 256 + f] = m2;
            s_out[g * 256 + 128 + f] = mean;
        } else {
            s_out[g * 256 + f] += m2;
            s_out[g * 256 + 128 + f] += mean;
        }
    }
}

// final MLP: 256->128->64->1 + sigmoid
__global__ void k_mlp(const float* __restrict__ s,
                      const float* __restrict__ W1, const float* __restrict__ b1,
                      const float* __restrict__ W2, const float* __restrict__ b2,
                      const float* __restrict__ W3, const float* __restrict__ b3,
                      float* __restrict__ out) {
    __shared__ float sh[256];
    __shared__ float h1[128];
    __shared__ float h2[64];
    __shared__ float red[128];
    int g = blockIdx.x, t = threadIdx.x;
    sh[t] = s[g * 256 + t];
    sh[t + 128] = s[g * 256 + 128 + t];
    __syncthreads();
    float acc = b1[t];
    for (int k = 0; k < 256; k++) acc += sh[k] * W1[k * 128 + t];
    h1[t] = fmaxf(acc, 0.f);
    __syncthreads();
    if (t < 64) {
        float a = b2[t];
        for (int k = 0; k < 128; k++) a += h1[k] * W2[k * 64 + t];
        h2[t] = fmaxf(a, 0.f);
    }
    __syncthreads();
    red[t] = (t < 64) ? h2[t] * W3[t] : 0.f;
    __syncthreads();
    for (int off = 64; off > 0; off >>= 1) {
        if (t < off) red[t] += red[t + off];
        __syncthreads();
    }
    if (t == 0) out[g] = 1.f / (1.f + expf(-(red[0] + b3[0])));
}

// ---------------- host orchestration ----------------
extern "C" void kernel_launch(void* const* d_in, const int* in_sizes, int n_in,
                              void* d_out, int out_size) {
    const float* x   = (const float*)d_in[0];
    const int*   ei  = (const int*)d_in[1];
    const int E = in_sizes[1] / 2;

    const float* Wl1 = (const float*)d_in[2];
    const float* bl1 = (const float*)d_in[3];
    const float* Wr1 = (const float*)d_in[4];
    const float* pw1 = (const float*)d_in[5];
    const float* Wl2 = (const float*)d_in[6];
    const float* bl2 = (const float*)d_in[7];
    const float* Wr2 = (const float*)d_in[8];
    const float* pw2 = (const float*)d_in[9];
    const float* Wl3 = (const float*)d_in[10];
    const float* bl3 = (const float*)d_in[11];
    const float* Wr3 = (const float*)d_in[12];
    const float* pw3 = (const float*)d_in[13];
    const float* W1  = (const float*)d_in[14];
    const float* b1  = (const float*)d_in[15];
    const float* W2  = (const float*)d_in[16];
    const float* b2  = (const float*)d_in[17];
    const float* W3  = (const float*)d_in[18];
    const float* b3  = (const float*)d_in[19];

    float *meanP, *hP, *poolA, *poolB, *scoreP, *sP;
    float2* bsP;
    int *newidP, *o2cP, *c2oP, *degP, *curP, *rpP, *nbrP, *partP, *offsP;
    cudaGetSymbolAddress((void**)&meanP, g_mean);
    cudaGetSymbolAddress((void**)&hP, g_h);
    cudaGetSymbolAddress((void**)&poolA, g_poolA);
    cudaGetSymbolAddress((void**)&poolB, g_poolB);
    cudaGetSymbolAddress((void**)&scoreP, g_score);
    cudaGetSymbolAddress((void**)&sP, g_s);
    cudaGetSymbolAddress((void**)&bsP, g_bsplit);
    cudaGetSymbolAddress((void**)&newidP, g_newid);
    cudaGetSymbolAddress((void**)&o2cP, g_orig2cur);
    cudaGetSymbolAddress((void**)&c2oP, g_cur2orig);
    cudaGetSymbolAddress((void**)&degP, g_deg);
    cudaGetSymbolAddress((void**)&curP, g_cursor);
    cudaGetSymbolAddress((void**)&rpP, g_rowptr);
    cudaGetSymbolAddress((void**)&nbrP, g_nbr);
    cudaGetSymbolAddress((void**)&partP, g_part);
    cudaGetSymbolAddress((void**)&offsP, g_offs);

    const int TB = 256;
    const int EB = (E + TB - 1) / TB;
    const int n0 = NMAX;

    // ---- one-time CSR build + map init + all-layer weight split ----
    k_zero_int<<<(n0 + TB - 1) / TB, TB>>>(degP, n0);
    k_count<<<EB, TB>>>(ei + E, E, degP);
    k_scan1<<<64, 1024>>>(degP, partP);
    k_scan2<<<1, 64>>>(partP, offsP);
    k_scan3<<<64, 1024>>>(degP, offsP, rpP, curP, o2cP, c2oP, n0);
    k_scatter<<<EB, TB>>>(ei, ei + E, E, curP, nbrP);
    k_splitB_all<<<384, 256>>>(Wl1, Wr1, Wl2, Wr2, Wl3, Wr3, bsP);

    struct LayerCfg {
        const float *xin, *bl, *pw;
        float* pool;
        int n, Npg, K, round;
    };
    LayerCfg layers[3] = {
        { x,     bl1, pw1, poolA, BGR * NPG0, NPG0, K1, 0 },
        { poolA, bl2, pw2, poolB, BGR * K1,   K1,   K2, 1 },
        { poolB, bl3, pw3, poolA, BGR * K2,   K2,   K3, 2 },
    };

    for (int L = 0; L < 3; L++) {
        LayerCfg& c = layers[L];
        int n = c.n;
        if (L == 0)
            k_aggregate1<<<(n * 32 + TB - 1) / TB, TB>>>(c.xin, rpP, nbrP, meanP, n);
        else
            k_aggregate<<<(n * 32 + TB - 1) / TB, TB>>>(c.xin, rpP, nbrP, c2oP, o2cP, meanP, n);
        k_gemm_v3<<<n / 128, 256>>>(meanP, c.xin, bsP + L * 256 * D128, c.bl, hP, n);
        k_score<<<(n * 32 + TB - 1) / TB, TB>>>(hP, c.pw, scoreP, n);
        k_topk<<<BGR, 1024>>>(scoreP, hP, c.pool, newidP, sP, o2cP, c2oP,
                              c.Npg, c.K, c.round, (L < 2) ? 1 : 0);
    }

    k_mlp<<<BGR, 128>>>(sP, W1, b1, W2, b2, W3, b3, (float*)d_out);
}

// round 8
// speedup vs baseline: 1.1246x; 1.1246x over previous
#include <cuda_runtime.h>
#include <math.h>
#include <stdint.h>

// ---------------- problem constants ----------------
#define D128 128
#define BGR 64
#define NPG0 1024
#define NMAX (BGR * NPG0)        // 65536
#define EMAX 1048576
#define K1 820                   // ceil(0.8*1024)
#define K2 656                   // ceil(0.8*820)
#define K3 525                   // ceil(0.8*656)

// ---------------- scratch (device globals; no allocations allowed) ----------------
__device__ float g_mean[NMAX * D128];
__device__ float g_h[NMAX * D128];
__device__ float g_poolA[BGR * K1 * D128];
__device__ float g_poolB[BGR * K2 * D128];
__device__ float g_score[NMAX];
__device__ int   g_newid[NMAX];
__device__ int   g_orig2cur[NMAX];
__device__ int   g_cur2orig[NMAX];
__device__ int   g_deg[NMAX];
__device__ int   g_cursor[NMAX];
__device__ int   g_rowptr[NMAX + 1];
__device__ int   g_nbr[EMAX];
__device__ int   g_part[64];
__device__ int   g_offs[64];
__device__ float g_bhi[3][256 * D128];
__device__ float g_blo[3][256 * D128];
__device__ float g_s[BGR * 256];

__device__ __forceinline__ void tf32_split(float v, uint32_t& hi, uint32_t& lo) {
    asm("cvt.rna.tf32.f32 %0, %1;" : "=r"(hi) : "f"(v));
    float r = v - __uint_as_float(hi);
    asm("cvt.rna.tf32.f32 %0, %1;" : "=r"(lo) : "f"(r));
}

__device__ __forceinline__ void mma_m16n8k8(float* c, const uint32_t* a, const uint32_t* b) {
    asm volatile(
        "mma.sync.aligned.m16n8k8.row.col.f32.tf32.tf32.f32 "
        "{%0,%1,%2,%3}, {%4,%5,%6,%7}, {%8,%9}, {%0,%1,%2,%3};"
        : "+f"(c[0]), "+f"(c[1]), "+f"(c[2]), "+f"(c[3])
        : "r"(a[0]), "r"(a[1]), "r"(a[2]), "r"(a[3]), "r"(b[0]), "r"(b[1]));
}

// ---------------- CSR build (once, on original graph) ----------------
__global__ void k_zero_int(int* p, int n) {
    int i = blockIdx.x * blockDim.x + threadIdx.x;
    if (i < n) p[i] = 0;
}

__global__ void k_count(const int* __restrict__ dst, int E, int* __restrict__ deg) {
    int e = blockIdx.x * blockDim.x + threadIdx.x;
    if (e < E) atomicAdd(&deg[dst[e]], 1);
}

__global__ void k_scan1(const int* __restrict__ deg, int* __restrict__ part) {
    __shared__ int s[1024];
    int t = threadIdx.x;
    s[t] = deg[blockIdx.x * 1024 + t];
    __syncthreads();
    for (int off = 512; off > 0; off >>= 1) {
        if (t < off) s[t] += s[t + off];
        __syncthreads();
    }
    if (t == 0) part[blockIdx.x] = s[0];
}

__global__ void k_scan2(const int* __restrict__ part, int* __restrict__ offs) {
    __shared__ int s[64];
    int t = threadIdx.x;
    int my = part[t];
    s[t] = my;
    __syncthreads();
    for (int off = 1; off < 64; off <<= 1) {
        int v = s[t];
        if (t >= off) v += s[t - off];
        __syncthreads();
        s[t] = v;
        __syncthreads();
    }
    offs[t] = s[t] - my;
}

// block-local scan + offsets; also initializes identity survival maps
__global__ void k_scan3(const int* __restrict__ deg, const int* __restrict__ offs,
                        int* __restrict__ rowptr, int* __restrict__ cursor,
                        int* __restrict__ o2c, int* __restrict__ c2o, int n) {
    __shared__ int s[1024];
    int t = threadIdx.x;
    int i = blockIdx.x * 1024 + t;
    int my = deg[i];
    s[t] = my;
    __syncthreads();
    for (int off = 1; off < 1024; off <<= 1) {
        int v = s[t];
        if (t >= off) v += s[t - off];
        __syncthreads();
        s[t] = v;
        __syncthreads();
    }
    int ex = s[t] - my + offs[blockIdx.x];
    rowptr[i] = ex;
    cursor[i] = ex;
    o2c[i] = i;
    c2o[i] = i;
    if (blockIdx.x == 63 && t == 1023) rowptr[n] = ex + my;
}

__global__ void k_scatter(const int* __restrict__ src, const int* __restrict__ dst, int E,
                          int* __restrict__ cursor, int* __restrict__ nbr) {
    int e = blockIdx.x * blockDim.x + threadIdx.x;
    if (e < E) {
        int p = atomicAdd(&cursor[dst[e]], 1);
        nbr[p] = src[e];
    }
}

// ---------------- mean aggregation ----------------
// Layer 1: identity maps — no indirection, no masks.
__global__ void k_aggregate1(const float* __restrict__ X, const int* __restrict__ rowptr,
                             const int* __restrict__ nbr, float* __restrict__ mean, int n) {
    int w = (blockIdx.x * blockDim.x + threadIdx.x) >> 5;
    int lane = threadIdx.x & 31;
    if (w >= n) return;
    int b = rowptr[w], e = rowptr[w + 1];
    float4 acc = make_float4(0.f, 0.f, 0.f, 0.f);
#pragma unroll 4
    for (int j = b; j < e; j++) {
        float4 v = ((const float4*)(X + (size_t)nbr[j] * D128))[lane];
        acc.x += v.x; acc.y += v.y; acc.z += v.z; acc.w += v.w;
    }
    int d = e - b;
    float inv = 1.0f / (float)(d > 0 ? d : 1);
    acc.x *= inv; acc.y *= inv; acc.z *= inv; acc.w *= inv;
    ((float4*)(mean + (size_t)w * D128))[lane] = acc;
}

// Layers 2/3: original CSR + survival maps, alive-masked (branchless, MLP-friendly).
__global__ void k_aggregate(const float* __restrict__ X, const int* __restrict__ rowptr,
                            const int* __restrict__ nbr, const int* __restrict__ c2o,
                            const int* __restrict__ o2c, float* __restrict__ mean, int n) {
    int w = (blockIdx.x * blockDim.x + threadIdx.x) >> 5;
    int lane = threadIdx.x & 31;
    if (w >= n) return;
    int o = c2o[w];
    int b = rowptr[o], e = rowptr[o + 1];
    float4 acc = make_float4(0.f, 0.f, 0.f, 0.f);
    float cnt = 0.f;
#pragma unroll 4
    for (int j = b; j < e; j++) {
        int c = o2c[nbr[j]];
        float wgt = (c >= 0) ? 1.f : 0.f;
        int idx = (c >= 0) ? c : 0;
        float4 v = ((const float4*)(X + (size_t)idx * D128))[lane];
        acc.x += wgt * v.x; acc.y += wgt * v.y;
        acc.z += wgt * v.z; acc.w += wgt * v.w;
        cnt += wgt;
    }
    float inv = 1.0f / fmaxf(cnt, 1.f);
    acc.x *= inv; acc.y *= inv; acc.z *= inv; acc.w *= inv;
    ((float4*)(mean + (size_t)w * D128))[lane] = acc;
}

// ---------------- weight pre-split for all 3 layers (one launch) ----------------
__global__ void k_splitB_all(const float* __restrict__ Wl1, const float* __restrict__ Wr1,
                             const float* __restrict__ Wl2, const float* __restrict__ Wr2,
                             const float* __restrict__ Wl3, const float* __restrict__ Wr3,
                             float* __restrict__ bh, float* __restrict__ bl) {
    int i = blockIdx.x * blockDim.x + threadIdx.x;   // 3 * 32768
    int l = i >> 15, j = i & 32767;
    const float* Wl = (l == 0) ? Wl1 : (l == 1) ? Wl2 : Wl3;
    const float* Wr = (l == 0) ? Wr1 : (l == 1) ? Wr2 : Wr3;
    float v = (j < 16384) ? Wl[j] : Wr[j - 16384];
    uint32_t hi, lo;
    tf32_split(v, hi, lo);
    bh[i] = __uint_as_float(hi);
    bl[i] = __uint_as_float(lo);
}

// ---------------- tf32 mma GEMM (R4/R6 version): H = relu([mean|x] @ [Wl;Wr] + bl) ----------------
#define ACH 16
#define ASTR 20
#define BSTR 136

__global__ void __launch_bounds__(256, 2)
k_gemm_mma(const float* __restrict__ Am, const float* __restrict__ Ax,
           const float* __restrict__ Bhi, const float* __restrict__ Blo,
           const float* __restrict__ bias, float* __restrict__ H, int n) {
    __shared__ float Ah[128 * ASTR];
    __shared__ float Al[128 * ASTR];
    __shared__ float Bh[ACH * BSTR];
    __shared__ float Bl[ACH * BSTR];
    int t = threadIdx.x, lane = t & 31, wid = t >> 5;
    int wm = (wid >> 2) * 64;
    int wn = (wid & 3) * 32;
    int m0 = blockIdx.x * 128;

    float c[4][4][4];
#pragma unroll
    for (int i = 0; i < 4; i++)
#pragma unroll
        for (int j = 0; j < 4; j++)
#pragma unroll
            for (int r = 0; r < 4; r++) c[i][j][r] = 0.f;

    int arow = t >> 1, acol0 = (t & 1) * 8;
    int brow = t >> 4, bcol0 = (t & 15) * 8;

    for (int ch = 0; ch < 16; ch++) {
        const float* A = (ch < 8) ? Am + (size_t)m0 * D128 + ch * ACH
                                  : Ax + (size_t)m0 * D128 + (ch - 8) * ACH;
#pragma unroll
        for (int q = 0; q < 2; q++) {
            float4 v = *(const float4*)(A + (size_t)arow * D128 + acol0 + q * 4);
            uint32_t h0, h1, h2, h3, l0, l1, l2, l3;
            tf32_split(v.x, h0, l0); tf32_split(v.y, h1, l1);
            tf32_split(v.z, h2, l2); tf32_split(v.w, h3, l3);
            float4 hv = make_float4(__uint_as_float(h0), __uint_as_float(h1),
                                    __uint_as_float(h2), __uint_as_float(h3));
            float4 lv = make_float4(__uint_as_float(l0), __uint_as_float(l1),
                                    __uint_as_float(l2), __uint_as_float(l3));
            *(float4*)(Ah + arow * ASTR + acol0 + q * 4) = hv;
            *(float4*)(Al + arow * ASTR + acol0 + q * 4) = lv;
        }
#pragma unroll
        for (int q = 0; q < 2; q++) {
            *(float4*)(Bh + brow * BSTR + bcol0 + q * 4) =
                *(const float4*)(Bhi + (size_t)(ch * ACH + brow) * D128 + bcol0 + q * 4);
            *(float4*)(Bl + brow * BSTR + bcol0 + q * 4) =
                *(const float4*)(Blo + (size_t)(ch * ACH + brow) * D128 + bcol0 + q * 4);
        }
        __syncthreads();

#pragma unroll
        for (int ks = 0; ks < 2; ks++) {
            uint32_t ah[4][4], bh[4][2];
#pragma unroll
            for (int mf = 0; mf < 4; mf++)
#pragma unroll
                for (int r = 0; r < 4; r++)
                    ah[mf][r] = __float_as_uint(
                        Ah[(wm + mf * 16 + (lane >> 2) + 8 * (r & 1)) * ASTR
                           + ks * 8 + (lane & 3) + 4 * (r >> 1)]);
#pragma unroll
            for (int nf = 0; nf < 4; nf++)
#pragma unroll
                for (int r = 0; r < 2; r++)
                    bh[nf][r] = __float_as_uint(
                        Bh[(ks * 8 + (lane & 3) + 4 * r) * BSTR + wn + nf * 8 + (lane >> 2)]);
#pragma unroll
            for (int mf = 0; mf < 4; mf++)
#pragma unroll
                for (int nf = 0; nf < 4; nf++)
                    mma_m16n8k8(c[mf][nf], ah[mf], bh[nf]);
            {
                uint32_t blo[4][2];
#pragma unroll
                for (int nf = 0; nf < 4; nf++)
#pragma unroll
                    for (int r = 0; r < 2; r++)
                        blo[nf][r] = __float_as_uint(
                            Bl[(ks * 8 + (lane & 3) + 4 * r) * BSTR + wn + nf * 8 + (lane >> 2)]);
#pragma unroll
                for (int mf = 0; mf < 4; mf++)
#pragma unroll
                    for (int nf = 0; nf < 4; nf++)
                        mma_m16n8k8(c[mf][nf], ah[mf], blo[nf]);
            }
            {
                uint32_t al[4][4];
#pragma unroll
                for (int mf = 0; mf < 4; mf++)
#pragma unroll
                    for (int r = 0; r < 4; r++)
                        al[mf][r] = __float_as_uint(
                            Al[(wm + mf * 16 + (lane >> 2) + 8 * (r & 1)) * ASTR
                               + ks * 8 + (lane & 3) + 4 * (r >> 1)]);
#pragma unroll
                for (int mf = 0; mf < 4; mf++)
#pragma unroll
                    for (int nf = 0; nf < 4; nf++)
                        mma_m16n8k8(c[mf][nf], al[mf], bh[nf]);
            }
        }
        __syncthreads();
    }

    int r0 = lane >> 2, cq = (lane & 3) * 2;
#pragma unroll
    for (int mf = 0; mf < 4; mf++) {
        int row = m0 + wm + mf * 16 + r0;
#pragma unroll
        for (int nf = 0; nf < 4; nf++) {
            int col = wn + nf * 8 + cq;
            float b0 = bias[col], b1 = bias[col + 1];
            float2 o0, o1;
            o0.x = fmaxf(c[mf][nf][0] + b0, 0.f);
            o0.y = fmaxf(c[mf][nf][1] + b1, 0.f);
            o1.x = fmaxf(c[mf][nf][2] + b0, 0.f);
            o1.y = fmaxf(c[mf][nf][3] + b1, 0.f);
            *(float2*)(H + (size_t)row * D128 + col) = o0;
            *(float2*)(H + (size_t)(row + 8) * D128 + col) = o1;
        }
    }
}

// score[i] = tanh(h_i . pw / ||pw||), one warp per row
__global__ void k_score(const float* __restrict__ H, const float* __restrict__ pw,
                        float* __restrict__ score, int n) {
    int w = (blockIdx.x * blockDim.x + threadIdx.x) >> 5;
    int lane = threadIdx.x & 31;
    if (w >= n) return;
    float4 h4 = ((const float4*)(H + (size_t)w * D128))[lane];
    float4 w4 = ((const float4*)pw)[lane];
    float dot = h4.x * w4.x + h4.y * w4.y + h4.z * w4.z + h4.w * w4.w;
    float nn = w4.x * w4.x + w4.y * w4.y + w4.z * w4.z + w4.w * w4.w;
#pragma unroll
    for (int off = 16; off > 0; off >>= 1) {
        dot += __shfl_xor_sync(0xFFFFFFFF, dot, off);
        nn  += __shfl_xor_sync(0xFFFFFFFF, nn, off);
    }
    if (lane == 0) score[w] = tanhf(dot / sqrtf(nn));
}

// per-graph bitonic top-K + fused pool write + readout + survival-map compose
__global__ void k_topk(const float* __restrict__ score, const float* __restrict__ H,
                       float* __restrict__ pool, int* __restrict__ newid,
                       float* __restrict__ s_out, int* __restrict__ o2c,
                       int* __restrict__ c2o, int Npg, int K, int round, int do_compose) {
    __shared__ float skey[1024];
    __shared__ int   sidx[1024];
    __shared__ float rmx[8][128];
    __shared__ float rsm[8][128];
    int g = blockIdx.x;
    int t = threadIdx.x;   // 1024 threads
    skey[t] = (t < Npg) ? score[g * Npg + t] : -INFINITY;
    sidx[t] = t;
    __syncthreads();
    for (int k = 2; k <= 1024; k <<= 1) {
        for (int j = k >> 1; j > 0; j >>= 1) {
            int ixj = t ^ j;
            if (ixj > t) {
                bool desc = ((t & k) == 0);
                float a = skey[t], b = skey[ixj];
                bool sw = desc ? (a < b) : (a > b);
                if (sw) {
                    skey[t] = b; skey[ixj] = a;
                    int tmp = sidx[t]; sidx[t] = sidx[ixj]; sidx[ixj] = tmp;
                }
            }
            __syncthreads();
        }
    }
    if (t < Npg) {
        int node = sidx[t];
        newid[g * Npg + node] = (t < K) ? (g * K + t) : -1;
    }
    __syncthreads();
    if (do_compose) {
        int o = g * NPG0 + t;
        int c = o2c[o];
        int nc = (c >= 0) ? newid[c] : -1;
        o2c[o] = nc;
        if (nc >= 0) c2o[nc] = o;
    }
    int f = t & 127, part = t >> 7;     // 8 parts x 128 features
    float mx = -INFINITY, sm = 0.f;
    for (int r = part; r < K; r += 8) {
        int node = sidx[r];
        float v = H[(size_t)(g * Npg + node) * D128 + f] * skey[r];
        pool[(size_t)(g * K + r) * D128 + f] = v;
        mx = fmaxf(mx, v);
        sm += v;
    }
    rmx[part][f] = mx; rsm[part][f] = sm;
    __syncthreads();
    if (t < 128) {
        float m2 = rmx[0][f], s2 = rsm[0][f];
#pragma unroll
        for (int p = 1; p < 8; p++) {
            m2 = fmaxf(m2, rmx[p][f]);
            s2 += rsm[p][f];
        }
        float mean = s2 / (float)K;
        if (round == 0) {
            s_out[g * 256 + f] = m2;
            s_out[g * 256 + 128 + f] = mean;
        } else {
            s_out[g * 256 + f] += m2;
            s_out[g * 256 + 128 + f] += mean;
        }
    }
}

// final MLP: 256->128->64->1 + sigmoid
__global__ void k_mlp(const float* __restrict__ s,
                      const float* __restrict__ W1, const float* __restrict__ b1,
                      const float* __restrict__ W2, const float* __restrict__ b2,
                      const float* __restrict__ W3, const float* __restrict__ b3,
                      float* __restrict__ out) {
    __shared__ float sh[256];
    __shared__ float h1[128];
    __shared__ float h2[64];
    __shared__ float red[128];
    int g = blockIdx.x, t = threadIdx.x;
    sh[t] = s[g * 256 + t];
    sh[t + 128] = s[g * 256 + 128 + t];
    __syncthreads();
    float acc = b1[t];
    for (int k = 0; k < 256; k++) acc += sh[k] * W1[k * 128 + t];
    h1[t] = fmaxf(acc, 0.f);
    __syncthreads();
    if (t < 64) {
        float a = b2[t];
        for (int k = 0; k < 128; k++) a += h1[k] * W2[k * 64 + t];
        h2[t] = fmaxf(a, 0.f);
    }
    __syncthreads();
    red[t] = (t < 64) ? h2[t] * W3[t] : 0.f;
    __syncthreads();
    for (int off = 64; off > 0; off >>= 1) {
        if (t < off) red[t] += red[t + off];
        __syncthreads();
    }
    if (t == 0) out[g] = 1.f / (1.f + expf(-(red[0] + b3[0])));
}

// ---------------- host orchestration ----------------
extern "C" void kernel_launch(void* const* d_in, const int* in_sizes, int n_in,
                              void* d_out, int out_size) {
    const float* x   = (const float*)d_in[0];
    const int*   ei  = (const int*)d_in[1];
    const int E = in_sizes[1] / 2;

    const float* Wl1 = (const float*)d_in[2];
    const float* bl1 = (const float*)d_in[3];
    const float* Wr1 = (const float*)d_in[4];
    const float* pw1 = (const float*)d_in[5];
    const float* Wl2 = (const float*)d_in[6];
    const float* bl2 = (const float*)d_in[7];
    const float* Wr2 = (const float*)d_in[8];
    const float* pw2 = (const float*)d_in[9];
    const float* Wl3 = (const float*)d_in[10];
    const float* bl3 = (const float*)d_in[11];
    const float* Wr3 = (const float*)d_in[12];
    const float* pw3 = (const float*)d_in[13];
    const float* W1  = (const float*)d_in[14];
    const float* b1  = (const float*)d_in[15];
    const float* W2  = (const float*)d_in[16];
    const float* b2  = (const float*)d_in[17];
    const float* W3  = (const float*)d_in[18];
    const float* b3  = (const float*)d_in[19];

    float *meanP, *hP, *poolA, *poolB, *scoreP, *sP, *bhiP, *bloP;
    int *newidP, *o2cP, *c2oP, *degP, *curP, *rpP, *nbrP, *partP, *offsP;
    cudaGetSymbolAddress((void**)&meanP, g_mean);
    cudaGetSymbolAddress((void**)&hP, g_h);
    cudaGetSymbolAddress((void**)&poolA, g_poolA);
    cudaGetSymbolAddress((void**)&poolB, g_poolB);
    cudaGetSymbolAddress((void**)&scoreP, g_score);
    cudaGetSymbolAddress((void**)&sP, g_s);
    cudaGetSymbolAddress((void**)&bhiP, g_bhi);
    cudaGetSymbolAddress((void**)&bloP, g_blo);
    cudaGetSymbolAddress((void**)&newidP, g_newid);
    cudaGetSymbolAddress((void**)&o2cP, g_orig2cur);
    cudaGetSymbolAddress((void**)&c2oP, g_cur2orig);
    cudaGetSymbolAddress((void**)&degP, g_deg);
    cudaGetSymbolAddress((void**)&curP, g_cursor);
    cudaGetSymbolAddress((void**)&rpP, g_rowptr);
    cudaGetSymbolAddress((void**)&nbrP, g_nbr);
    cudaGetSymbolAddress((void**)&partP, g_part);
    cudaGetSymbolAddress((void**)&offsP, g_offs);

    const int TB = 256;
    const int EB = (E + TB - 1) / TB;
    const int n0 = NMAX;

    // ---- one-time CSR build + map init + all-layer weight split ----
    k_zero_int<<<(n0 + TB - 1) / TB, TB>>>(degP, n0);
    k_count<<<EB, TB>>>(ei + E, E, degP);
    k_scan1<<<64, 1024>>>(degP, partP);
    k_scan2<<<1, 64>>>(partP, offsP);
    k_scan3<<<64, 1024>>>(degP, offsP, rpP, curP, o2cP, c2oP, n0);
    k_scatter<<<EB, TB>>>(ei, ei + E, E, curP, nbrP);
    k_splitB_all<<<384, 256>>>(Wl1, Wr1, Wl2, Wr2, Wl3, Wr3, bhiP, bloP);

    struct LayerCfg {
        const float *xin, *bl, *pw;
        float* pool;
        int n, Npg, K, round;
    };
    LayerCfg layers[3] = {
        { x,     bl1, pw1, poolA, BGR * NPG0, NPG0, K1, 0 },
        { poolA, bl2, pw2, poolB, BGR * K1,   K1,   K2, 1 },
        { poolB, bl3, pw3, poolA, BGR * K2,   K2,   K3, 2 },
    };

    for (int L = 0; L < 3; L++) {
        LayerCfg& c = layers[L];
        int n = c.n;
        if (L == 0)
            k_aggregate1<<<(n * 32 + TB - 1) / TB, TB>>>(c.xin, rpP, nbrP, meanP, n);
        else
            k_aggregate<<<(n * 32 + TB - 1) / TB, TB>>>(c.xin, rpP, nbrP, c2oP, o2cP, meanP, n);
        k_gemm_mma<<<n / 128, 256>>>(meanP, c.xin, bhiP + L * 256 * D128,
                                     bloP + L * 256 * D128, c.bl, hP, n);
        k_score<<<(n * 32 + TB - 1) / TB, TB>>>(hP, c.pw, scoreP, n);
        k_topk<<<BGR, 1024>>>(scoreP, hP, c.pool, newidP, sP, o2cP, c2oP,
                              c.Npg, c.K, c.round, (L < 2) ? 1 : 0);
    }

    k_mlp<<<BGR, 128>>>(sP, W1, b1, W2, b2, W3, b3, (float*)d_out);
}

// round 9
// speedup vs baseline: 1.1930x; 1.0608x over previous
#include <cuda_runtime.h>
#include <math.h>
#include <stdint.h>

// ---------------- problem constants ----------------
#define D128 128
#define BGR 64
#define NPG0 1024
#define NMAX (BGR * NPG0)        // 65536
#define EMAX 1048576
#define K1 820                   // ceil(0.8*1024)
#define K2 656                   // ceil(0.8*820)
#define K3 525                   // ceil(0.8*656)

// ---------------- scratch (device globals; no allocations allowed) ----------------
__device__ float g_mean[NMAX * D128];
__device__ float g_h[NMAX * D128];
__device__ float g_poolA[BGR * K1 * D128];
__device__ float g_poolB[BGR * K2 * D128];
__device__ float g_score[NMAX];
__device__ int   g_newid[NMAX];
__device__ int   g_orig2cur[NMAX];
__device__ int   g_cur2orig[NMAX];
__device__ int   g_deg[NMAX];
__device__ int   g_cursor[NMAX];
__device__ int   g_rowptr[NMAX + 1];
__device__ int   g_nbr[EMAX];
__device__ int   g_part[64];
__device__ float g_bhi[3][256 * D128];
__device__ float g_blo[3][256 * D128];
__device__ float g_s[BGR * 256];

__device__ __forceinline__ void tf32_split(float v, uint32_t& hi, uint32_t& lo) {
    asm("cvt.rna.tf32.f32 %0, %1;" : "=r"(hi) : "f"(v));
    float r = v - __uint_as_float(hi);
    asm("cvt.rna.tf32.f32 %0, %1;" : "=r"(lo) : "f"(r));
}

__device__ __forceinline__ void mma_m16n8k8(float* c, const uint32_t* a, const uint32_t* b) {
    asm volatile(
        "mma.sync.aligned.m16n8k8.row.col.f32.tf32.tf32.f32 "
        "{%0,%1,%2,%3}, {%4,%5,%6,%7}, {%8,%9}, {%0,%1,%2,%3};"
        : "+f"(c[0]), "+f"(c[1]), "+f"(c[2]), "+f"(c[3])
        : "r"(a[0]), "r"(a[1]), "r"(a[2]), "r"(a[3]), "r"(b[0]), "r"(b[1]));
}

// ---------------- CSR build (once, on original graph) ----------------
__global__ void k_zero_int(int* p, int n) {
    int i = blockIdx.x * blockDim.x + threadIdx.x;
    if (i < n) p[i] = 0;
}

__global__ void k_count(const int* __restrict__ dst, int E, int* __restrict__ deg) {
    int e = blockIdx.x * blockDim.x + threadIdx.x;
    if (e < E) atomicAdd(&deg[dst[e]], 1);
}

__global__ void k_scan1(const int* __restrict__ deg, int* __restrict__ part) {
    __shared__ int s[1024];
    int t = threadIdx.x;
    s[t] = deg[blockIdx.x * 1024 + t];
    __syncthreads();
    for (int off = 512; off > 0; off >>= 1) {
        if (t < off) s[t] += s[t + off];
        __syncthreads();
    }
    if (t == 0) part[blockIdx.x] = s[0];
}

// block-local scan + per-block offset (folded scan2) + identity survival-map init
__global__ void k_scan3(const int* __restrict__ deg, const int* __restrict__ part,
                        int* __restrict__ rowptr, int* __restrict__ cursor,
                        int* __restrict__ o2c, int* __restrict__ c2o, int n) {
    __shared__ int s[1024];
    __shared__ int soff[64];
    int t = threadIdx.x;
    int i = blockIdx.x * 1024 + t;
    int my = deg[i];
    s[t] = my;
    if (t < 64) soff[t] = part[t];
    __syncthreads();
    if (t == 0) {
        int run = 0;
#pragma unroll 8
        for (int b = 0; b < 64; b++) { int v = soff[b]; soff[b] = run; run += v; }
    }
    for (int off = 1; off < 1024; off <<= 1) {
        int v = s[t];
        if (t >= off) v += s[t - off];
        __syncthreads();
        s[t] = v;
        __syncthreads();
    }
    int ex = s[t] - my + soff[blockIdx.x];
    rowptr[i] = ex;
    cursor[i] = ex;
    o2c[i] = i;
    c2o[i] = i;
    if (blockIdx.x == 63 && t == 1023) rowptr[n] = ex + my;
}

__global__ void k_scatter(const int* __restrict__ src, const int* __restrict__ dst, int E,
                          int* __restrict__ cursor, int* __restrict__ nbr) {
    int e = blockIdx.x * blockDim.x + threadIdx.x;
    if (e < E) {
        int p = atomicAdd(&cursor[dst[e]], 1);
        nbr[p] = src[e];
    }
}

// ---------------- mean aggregation ----------------
__global__ void k_aggregate1(const float* __restrict__ X, const int* __restrict__ rowptr,
                             const int* __restrict__ nbr, float* __restrict__ mean, int n) {
    int w = (blockIdx.x * blockDim.x + threadIdx.x) >> 5;
    int lane = threadIdx.x & 31;
    if (w >= n) return;
    int b = rowptr[w], e = rowptr[w + 1];
    float4 acc = make_float4(0.f, 0.f, 0.f, 0.f);
#pragma unroll 4
    for (int j = b; j < e; j++) {
        float4 v = ((const float4*)(X + (size_t)nbr[j] * D128))[lane];
        acc.x += v.x; acc.y += v.y; acc.z += v.z; acc.w += v.w;
    }
    int d = e - b;
    float inv = 1.0f / (float)(d > 0 ? d : 1);
    acc.x *= inv; acc.y *= inv; acc.z *= inv; acc.w *= inv;
    ((float4*)(mean + (size_t)w * D128))[lane] = acc;
}

__global__ void k_aggregate(const float* __restrict__ X, const int* __restrict__ rowptr,
                            const int* __restrict__ nbr, const int* __restrict__ c2o,
                            const int* __restrict__ o2c, float* __restrict__ mean, int n) {
    int w = (blockIdx.x * blockDim.x + threadIdx.x) >> 5;
    int lane = threadIdx.x & 31;
    if (w >= n) return;
    int o = c2o[w];
    int b = rowptr[o], e = rowptr[o + 1];
    float4 acc = make_float4(0.f, 0.f, 0.f, 0.f);
    float cnt = 0.f;
#pragma unroll 4
    for (int j = b; j < e; j++) {
        int c = o2c[nbr[j]];
        float wgt = (c >= 0) ? 1.f : 0.f;
        int idx = (c >= 0) ? c : 0;
        float4 v = ((const float4*)(X + (size_t)idx * D128))[lane];
        acc.x += wgt * v.x; acc.y += wgt * v.y;
        acc.z += wgt * v.z; acc.w += wgt * v.w;
        cnt += wgt;
    }
    float inv = 1.0f / fmaxf(cnt, 1.f);
    acc.x *= inv; acc.y *= inv; acc.z *= inv; acc.w *= inv;
    ((float4*)(mean + (size_t)w * D128))[lane] = acc;
}

// ---------------- weight pre-split for all 3 layers (one launch) ----------------
__global__ void k_splitB_all(const float* __restrict__ Wl1, const float* __restrict__ Wr1,
                             const float* __restrict__ Wl2, const float* __restrict__ Wr2,
                             const float* __restrict__ Wl3, const float* __restrict__ Wr3,
                             float* __restrict__ bh, float* __restrict__ bl) {
    int i = blockIdx.x * blockDim.x + threadIdx.x;   // 3 * 32768
    int l = i >> 15, j = i & 32767;
    const float* Wl = (l == 0) ? Wl1 : (l == 1) ? Wl2 : Wl3;
    const float* Wr = (l == 0) ? Wr1 : (l == 1) ? Wr2 : Wr3;
    float v = (j < 16384) ? Wl[j] : Wr[j - 16384];
    uint32_t hi, lo;
    tf32_split(v, hi, lo);
    bh[i] = __uint_as_float(hi);
    bl[i] = __uint_as_float(lo);
}

// ---------------- tf32 mma GEMM + fused score epilogue ----------------
// H = relu([mean|x] @ [Wl;Wr] + bl);  score = tanh(H . pw / ||pw||)
#define ACH 16
#define ASTR 20
#define BSTR 136

__global__ void __launch_bounds__(256, 2)
k_gemm_mma(const float* __restrict__ Am, const float* __restrict__ Ax,
           const float* __restrict__ Bhi, const float* __restrict__ Blo,
           const float* __restrict__ bias, const float* __restrict__ pw,
           float* __restrict__ H, float* __restrict__ score, int n) {
    __shared__ float Ah[128 * ASTR];
    __shared__ float Al[128 * ASTR];
    __shared__ float Bh[ACH * BSTR];
    __shared__ float Bl[ACH * BSTR];
    __shared__ float s_rnorm;
    int t = threadIdx.x, lane = t & 31, wid = t >> 5;
    int wm = (wid >> 2) * 64;
    int wn = (wid & 3) * 32;
    int m0 = blockIdx.x * 128;

    // ||pw|| (warp 0); first loop barrier orders it before epilogue use
    if (t < 32) {
        float4 w4 = ((const float4*)pw)[t];
        float nn = w4.x * w4.x + w4.y * w4.y + w4.z * w4.z + w4.w * w4.w;
#pragma unroll
        for (int off = 16; off > 0; off >>= 1)
            nn += __shfl_xor_sync(0xFFFFFFFF, nn, off);
        if (t == 0) s_rnorm = 1.0f / sqrtf(nn);
    }

    float c[4][4][4];
#pragma unroll
    for (int i = 0; i < 4; i++)
#pragma unroll
        for (int j = 0; j < 4; j++)
#pragma unroll
            for (int r = 0; r < 4; r++) c[i][j][r] = 0.f;

    int arow = t >> 1, acol0 = (t & 1) * 8;
    int brow = t >> 4, bcol0 = (t & 15) * 8;

    for (int ch = 0; ch < 16; ch++) {
        const float* A = (ch < 8) ? Am + (size_t)m0 * D128 + ch * ACH
                                  : Ax + (size_t)m0 * D128 + (ch - 8) * ACH;
#pragma unroll
        for (int q = 0; q < 2; q++) {
            float4 v = *(const float4*)(A + (size_t)arow * D128 + acol0 + q * 4);
            uint32_t h0, h1, h2, h3, l0, l1, l2, l3;
            tf32_split(v.x, h0, l0); tf32_split(v.y, h1, l1);
            tf32_split(v.z, h2, l2); tf32_split(v.w, h3, l3);
            float4 hv = make_float4(__uint_as_float(h0), __uint_as_float(h1),
                                    __uint_as_float(h2), __uint_as_float(h3));
            float4 lv = make_float4(__uint_as_float(l0), __uint_as_float(l1),
                                    __uint_as_float(l2), __uint_as_float(l3));
            *(float4*)(Ah + arow * ASTR + acol0 + q * 4) = hv;
            *(float4*)(Al + arow * ASTR + acol0 + q * 4) = lv;
        }
#pragma unroll
        for (int q = 0; q < 2; q++) {
            *(float4*)(Bh + brow * BSTR + bcol0 + q * 4) =
                *(const float4*)(Bhi + (size_t)(ch * ACH + brow) * D128 + bcol0 + q * 4);
            *(float4*)(Bl + brow * BSTR + bcol0 + q * 4) =
                *(const float4*)(Blo + (size_t)(ch * ACH + brow) * D128 + bcol0 + q * 4);
        }
        __syncthreads();

#pragma unroll
        for (int ks = 0; ks < 2; ks++) {
            uint32_t ah[4][4], bh[4][2];
#pragma unroll
            for (int mf = 0; mf < 4; mf++)
#pragma unroll
                for (int r = 0; r < 4; r++)
                    ah[mf][r] = __float_as_uint(
                        Ah[(wm + mf * 16 + (lane >> 2) + 8 * (r & 1)) * ASTR
                           + ks * 8 + (lane & 3) + 4 * (r >> 1)]);
#pragma unroll
            for (int nf = 0; nf < 4; nf++)
#pragma unroll
                for (int r = 0; r < 2; r++)
                    bh[nf][r] = __float_as_uint(
                        Bh[(ks * 8 + (lane & 3) + 4 * r) * BSTR + wn + nf * 8 + (lane >> 2)]);
#pragma unroll
            for (int mf = 0; mf < 4; mf++)
#pragma unroll
                for (int nf = 0; nf < 4; nf++)
                    mma_m16n8k8(c[mf][nf], ah[mf], bh[nf]);
            {
                uint32_t blo[4][2];
#pragma unroll
                for (int nf = 0; nf < 4; nf++)
#pragma unroll
                    for (int r = 0; r < 2; r++)
                        blo[nf][r] = __float_as_uint(
                            Bl[(ks * 8 + (lane & 3) + 4 * r) * BSTR + wn + nf * 8 + (lane >> 2)]);
#pragma unroll
                for (int mf = 0; mf < 4; mf++)
#pragma unroll
                    for (int nf = 0; nf < 4; nf++)
                        mma_m16n8k8(c[mf][nf], ah[mf], blo[nf]);
            }
            {
                uint32_t al[4][4];
#pragma unroll
                for (int mf = 0; mf < 4; mf++)
#pragma unroll
                    for (int r = 0; r < 4; r++)
                        al[mf][r] = __float_as_uint(
                            Al[(wm + mf * 16 + (lane >> 2) + 8 * (r & 1)) * ASTR
                               + ks * 8 + (lane & 3) + 4 * (r >> 1)]);
#pragma unroll
                for (int mf = 0; mf < 4; mf++)
#pragma unroll
                    for (int nf = 0; nf < 4; nf++)
                        mma_m16n8k8(c[mf][nf], al[mf], bh[nf]);
            }
        }
        __syncthreads();
    }

    // ---- epilogue: bias + relu + H store + fused score ----
    int r0 = lane >> 2, cq = (lane & 3) * 2;
    float pwv[4][2];
#pragma unroll
    for (int nf = 0; nf < 4; nf++) {
        pwv[nf][0] = pw[wn + nf * 8 + cq];
        pwv[nf][1] = pw[wn + nf * 8 + cq + 1];
    }
    float* sdot = Bh;   // reuse: [128][4]
#pragma unroll
    for (int mf = 0; mf < 4; mf++) {
        int row = m0 + wm + mf * 16 + r0;
        float p0 = 0.f, p1 = 0.f;
#pragma unroll
        for (int nf = 0; nf < 4; nf++) {
            int col = wn + nf * 8 + cq;
            float b0 = bias[col], b1 = bias[col + 1];
            float2 o0, o1;
            o0.x = fmaxf(c[mf][nf][0] + b0, 0.f);
            o0.y = fmaxf(c[mf][nf][1] + b1, 0.f);
            o1.x = fmaxf(c[mf][nf][2] + b0, 0.f);
            o1.y = fmaxf(c[mf][nf][3] + b1, 0.f);
            *(float2*)(H + (size_t)row * D128 + col) = o0;
            *(float2*)(H + (size_t)(row + 8) * D128 + col) = o1;
            p0 += o0.x * pwv[nf][0] + o0.y * pwv[nf][1];
            p1 += o1.x * pwv[nf][0] + o1.y * pwv[nf][1];
        }
        // reduce over the 4-lane column group (lane bits 0-1)
        p0 += __shfl_xor_sync(0xFFFFFFFF, p0, 1);
        p0 += __shfl_xor_sync(0xFFFFFFFF, p0, 2);
        p1 += __shfl_xor_sync(0xFFFFFFFF, p1, 1);
        p1 += __shfl_xor_sync(0xFFFFFFFF, p1, 2);
        if ((lane & 3) == 0) {
            int rr = wm + mf * 16 + r0;
            sdot[rr * 4 + (wid & 3)] = p0;
            sdot[(rr + 8) * 4 + (wid & 3)] = p1;
        }
    }
    __syncthreads();
    if (t < 128) {
        float4 d4 = *(float4*)&sdot[t * 4];
        float dot = d4.x + d4.y + d4.z + d4.w;
        score[m0 + t] = tanhf(dot * s_rnorm);
    }
}

// per-graph bitonic top-K + fused pool write + readout + survival-map compose
__global__ void k_topk(const float* __restrict__ score, const float* __restrict__ H,
                       float* __restrict__ pool, int* __restrict__ newid,
                       float* __restrict__ s_out, int* __restrict__ o2c,
                       int* __restrict__ c2o, int Npg, int K, int round, int do_compose) {
    __shared__ float skey[1024];
    __shared__ int   sidx[1024];
    __shared__ float rmx[8][128];
    __shared__ float rsm[8][128];
    int g = blockIdx.x;
    int t = threadIdx.x;   // 1024 threads
    skey[t] = (t < Npg) ? score[g * Npg + t] : -INFINITY;
    sidx[t] = t;
    __syncthreads();
    for (int k = 2; k <= 1024; k <<= 1) {
        for (int j = k >> 1; j > 0; j >>= 1) {
            int ixj = t ^ j;
            if (ixj > t) {
                bool desc = ((t & k) == 0);
                float a = skey[t], b = skey[ixj];
                bool sw = desc ? (a < b) : (a > b);
                if (sw) {
                    skey[t] = b; skey[ixj] = a;
                    int tmp = sidx[t]; sidx[t] = sidx[ixj]; sidx[ixj] = tmp;
                }
            }
            __syncthreads();
        }
    }
    if (t < Npg) {
        int node = sidx[t];
        newid[g * Npg + node] = (t < K) ? (g * K + t) : -1;
    }
    __syncthreads();
    if (do_compose) {
        int o = g * NPG0 + t;
        int c = o2c[o];
        int nc = (c >= 0) ? newid[c] : -1;
        o2c[o] = nc;
        if (nc >= 0) c2o[nc] = o;
    }
    int f = t & 127, part = t >> 7;     // 8 parts x 128 features
    float mx = -INFINITY, sm = 0.f;
    for (int r = part; r < K; r += 8) {
        int node = sidx[r];
        float v = H[(size_t)(g * Npg + node) * D128 + f] * skey[r];
        pool[(size_t)(g * K + r) * D128 + f] = v;
        mx = fmaxf(mx, v);
        sm += v;
    }
    rmx[part][f] = mx; rsm[part][f] = sm;
    __syncthreads();
    if (t < 128) {
        float m2 = rmx[0][f], s2 = rsm[0][f];
#pragma unroll
        for (int p = 1; p < 8; p++) {
            m2 = fmaxf(m2, rmx[p][f]);
            s2 += rsm[p][f];
        }
        float mean = s2 / (float)K;
        if (round == 0) {
            s_out[g * 256 + f] = m2;
            s_out[g * 256 + 128 + f] = mean;
        } else {
            s_out[g * 256 + f] += m2;
            s_out[g * 256 + 128 + f] += mean;
        }
    }
}

// final MLP: 256->128->64->1 + sigmoid
__global__ void k_mlp(const float* __restrict__ s,
                      const float* __restrict__ W1, const float* __restrict__ b1,
                      const float* __restrict__ W2, const float* __restrict__ b2,
                      const float* __restrict__ W3, const float* __restrict__ b3,
                      float* __restrict__ out) {
    __shared__ float sh[256];
    __shared__ float h1[128];
    __shared__ float h2[64];
    __shared__ float red[128];
    int g = blockIdx.x, t = threadIdx.x;
    sh[t] = s[g * 256 + t];
    sh[t + 128] = s[g * 256 + 128 + t];
    __syncthreads();
    float acc = b1[t];
    for (int k = 0; k < 256; k++) acc += sh[k] * W1[k * 128 + t];
    h1[t] = fmaxf(acc, 0.f);
    __syncthreads();
    if (t < 64) {
        float a = b2[t];
        for (int k = 0; k < 128; k++) a += h1[k] * W2[k * 64 + t];
        h2[t] = fmaxf(a, 0.f);
    }
    __syncthreads();
    red[t] = (t < 64) ? h2[t] * W3[t] : 0.f;
    __syncthreads();
    for (int off = 64; off > 0; off >>= 1) {
        if (t < off) red[t] += red[t + off];
        __syncthreads();
    }
    if (t == 0) out[g] = 1.f / (1.f + expf(-(red[0] + b3[0])));
}

// ---------------- host orchestration ----------------
extern "C" void kernel_launch(void* const* d_in, const int* in_sizes, int n_in,
                              void* d_out, int out_size) {
    const float* x   = (const float*)d_in[0];
    const int*   ei  = (const int*)d_in[1];
    const int E = in_sizes[1] / 2;

    const float* Wl1 = (const float*)d_in[2];
    const float* bl1 = (const float*)d_in[3];
    const float* Wr1 = (const float*)d_in[4];
    const float* pw1 = (const float*)d_in[5];
    const float* Wl2 = (const float*)d_in[6];
    const float* bl2 = (const float*)d_in[7];
    const float* Wr2 = (const float*)d_in[8];
    const float* pw2 = (const float*)d_in[9];
    const float* Wl3 = (const float*)d_in[10];
    const float* bl3 = (const float*)d_in[11];
    const float* Wr3 = (const float*)d_in[12];
    const float* pw3 = (const float*)d_in[13];
    const float* W1  = (const float*)d_in[14];
    const float* b1  = (const float*)d_in[15];
    const float* W2  = (const float*)d_in[16];
    const float* b2  = (const float*)d_in[17];
    const float* W3  = (const float*)d_in[18];
    const float* b3  = (const float*)d_in[19];

    float *meanP, *hP, *poolA, *poolB, *scoreP, *sP, *bhiP, *bloP;
    int *newidP, *o2cP, *c2oP, *degP, *curP, *rpP, *nbrP, *partP;
    cudaGetSymbolAddress((void**)&meanP, g_mean);
    cudaGetSymbolAddress((void**)&hP, g_h);
    cudaGetSymbolAddress((void**)&poolA, g_poolA);
    cudaGetSymbolAddress((void**)&poolB, g_poolB);
    cudaGetSymbolAddress((void**)&scoreP, g_score);
    cudaGetSymbolAddress((void**)&sP, g_s);
    cudaGetSymbolAddress((void**)&bhiP, g_bhi);
    cudaGetSymbolAddress((void**)&bloP, g_blo);
    cudaGetSymbolAddress((void**)&newidP, g_newid);
    cudaGetSymbolAddress((void**)&o2cP, g_orig2cur);
    cudaGetSymbolAddress((void**)&c2oP, g_cur2orig);
    cudaGetSymbolAddress((void**)&degP, g_deg);
    cudaGetSymbolAddress((void**)&curP, g_cursor);
    cudaGetSymbolAddress((void**)&rpP, g_rowptr);
    cudaGetSymbolAddress((void**)&nbrP, g_nbr);
    cudaGetSymbolAddress((void**)&partP, g_part);

    const int TB = 256;
    const int EB = (E + TB - 1) / TB;
    const int n0 = NMAX;

    // ---- one-time CSR build + map init + all-layer weight split ----
    k_zero_int<<<(n0 + TB - 1) / TB, TB>>>(degP, n0);
    k_count<<<EB, TB>>>(ei + E, E, degP);
    k_scan1<<<64, 1024>>>(degP, partP);
    k_scan3<<<64, 1024>>>(degP, partP, rpP, curP, o2cP, c2oP, n0);
    k_scatter<<<EB, TB>>>(ei, ei + E, E, curP, nbrP);
    k_splitB_all<<<384, 256>>>(Wl1, Wr1, Wl2, Wr2, Wl3, Wr3, bhiP, bloP);

    struct LayerCfg {
        const float *xin, *bl, *pw;
        float* pool;
        int n, Npg, K, round;
    };
    LayerCfg layers[3] = {
        { x,     bl1, pw1, poolA, BGR * NPG0, NPG0, K1, 0 },
        { poolA, bl2, pw2, poolB, BGR * K1,   K1,   K2, 1 },
        { poolB, bl3, pw3, poolA, BGR * K2,   K2,   K3, 2 },
    };

    for (int L = 0; L < 3; L++) {
        LayerCfg& c = layers[L];
        int n = c.n;
        if (L == 0)
            k_aggregate1<<<(n * 32 + TB - 1) / TB, TB>>>(c.xin, rpP, nbrP, meanP, n);
        else
            k_aggregate<<<(n * 32 + TB - 1) / TB, TB>>>(c.xin, rpP, nbrP, c2oP, o2cP, meanP, n);
        k_gemm_mma<<<n / 128, 256>>>(meanP, c.xin, bhiP + L * 256 * D128,
                                     bloP + L * 256 * D128, c.bl, c.pw, hP, scoreP, n);
        k_topk<<<BGR, 1024>>>(scoreP, hP, c.pool, newidP, sP, o2cP, c2oP,
                              c.Npg, c.K, c.round, (L < 2) ? 1 : 0);
    }

    k_mlp<<<BGR, 128>>>(sP, W1, b1, W2, b2, W3, b3, (float*)d_out);
}

// round 10
// speedup vs baseline: 1.2357x; 1.0358x over previous
#include <cuda_runtime.h>
#include <math.h>
#include <stdint.h>

// ---------------- problem constants ----------------
#define D128 128
#define BGR 64
#define NPG0 1024
#define NMAX (BGR * NPG0)        // 65536
#define EMAX 1048576
#define K1 820                   // ceil(0.8*1024)
#define K2 656                   // ceil(0.8*820)
#define K3 525                   // ceil(0.8*656)

// ---------------- scratch (device globals; no allocations allowed) ----------------
__device__ float g_mean[NMAX * D128];
__device__ float g_h[NMAX * D128];
__device__ float g_poolA[BGR * K1 * D128];
__device__ float g_poolB[BGR * K2 * D128];
__device__ float g_score[NMAX];
__device__ int   g_newid[NMAX];
__device__ int   g_orig2cur[NMAX];
__device__ int   g_cur2orig[NMAX];
__device__ int   g_rowptr[NMAX + 1];
__device__ int   g_nbr[EMAX];
__device__ float g_bhi[3][256 * D128];
__device__ float g_blo[3][256 * D128];
__device__ float g_s[BGR * 256];

__device__ __forceinline__ void tf32_split(float v, uint32_t& hi, uint32_t& lo) {
    asm("cvt.rna.tf32.f32 %0, %1;" : "=r"(hi) : "f"(v));
    float r = v - __uint_as_float(hi);
    asm("cvt.rna.tf32.f32 %0, %1;" : "=r"(lo) : "f"(r));
}

__device__ __forceinline__ void mma_m16n8k8(float* c, const uint32_t* a, const uint32_t* b) {
    asm volatile(
        "mma.sync.aligned.m16n8k8.row.col.f32.tf32.tf32.f32 "
        "{%0,%1,%2,%3}, {%4,%5,%6,%7}, {%8,%9}, {%0,%1,%2,%3};"
        : "+f"(c[0]), "+f"(c[1]), "+f"(c[2]), "+f"(c[3])
        : "r"(a[0]), "r"(a[1]), "r"(a[2]), "r"(a[3]), "r"(b[0]), "r"(b[1]));
}

// ---------------- CSR build: one block per graph, all in SMEM ----------------
// Edges [g*epg, (g+1)*epg) belong to graph g (per reference setup). Count with
// SMEM atomics, Hillis-Steele scan, scatter via SMEM cursors into the graph's
// contiguous nbr segment. Also initializes identity survival maps.
__global__ void __launch_bounds__(1024)
k_csr(const int* __restrict__ src, const int* __restrict__ dst, int epg,
      int* __restrict__ rowptr, int* __restrict__ nbr,
      int* __restrict__ o2c, int* __restrict__ c2o) {
    __shared__ int deg[1024];
    __shared__ int cur[1024];
    int g = blockIdx.x, t = threadIdx.x;
    int ebase = g * epg;
    int nbase = g * NPG0;

    deg[t] = 0;
    __syncthreads();
    // count (coalesced edge reads, SMEM atomics)
    for (int e = ebase + t; e < ebase + epg; e += 1024)
        atomicAdd(&deg[dst[e] - nbase], 1);
    __syncthreads();
    // inclusive scan of 1024
    int my = deg[t];
    cur[t] = my;
    __syncthreads();
    for (int off = 1; off < 1024; off <<= 1) {
        int v = cur[t];
        if (t >= off) v += cur[t - off];
        __syncthreads();
        cur[t] = v;
        __syncthreads();
    }
    int ex = cur[t] - my;   // exclusive prefix within graph
    rowptr[nbase + t] = ebase + ex;
    o2c[nbase + t] = nbase + t;
    c2o[nbase + t] = nbase + t;
    if (g == 0 && t == 0) rowptr[NMAX] = BGR * epg;
    __syncthreads();
    cur[t] = ex;            // cursors
    __syncthreads();
    // scatter via SMEM cursors
    for (int e = ebase + t; e < ebase + epg; e += 1024) {
        int d = dst[e] - nbase;
        int p = atomicAdd(&cur[d], 1);
        nbr[ebase + p] = src[e];
    }
}

// ---------------- mean aggregation ----------------
__global__ void k_aggregate1(const float* __restrict__ X, const int* __restrict__ rowptr,
                             const int* __restrict__ nbr, float* __restrict__ mean, int n) {
    int w = (blockIdx.x * blockDim.x + threadIdx.x) >> 5;
    int lane = threadIdx.x & 31;
    if (w >= n) return;
    int b = rowptr[w], e = rowptr[w + 1];
    float4 acc = make_float4(0.f, 0.f, 0.f, 0.f);
#pragma unroll 4
    for (int j = b; j < e; j++) {
        float4 v = ((const float4*)(X + (size_t)nbr[j] * D128))[lane];
        acc.x += v.x; acc.y += v.y; acc.z += v.z; acc.w += v.w;
    }
    int d = e - b;
    float inv = 1.0f / (float)(d > 0 ? d : 1);
    acc.x *= inv; acc.y *= inv; acc.z *= inv; acc.w *= inv;
    ((float4*)(mean + (size_t)w * D128))[lane] = acc;
}

__global__ void k_aggregate(const float* __restrict__ X, const int* __restrict__ rowptr,
                            const int* __restrict__ nbr, const int* __restrict__ c2o,
                            const int* __restrict__ o2c, float* __restrict__ mean, int n) {
    int w = (blockIdx.x * blockDim.x + threadIdx.x) >> 5;
    int lane = threadIdx.x & 31;
    if (w >= n) return;
    int o = c2o[w];
    int b = rowptr[o], e = rowptr[o + 1];
    float4 acc = make_float4(0.f, 0.f, 0.f, 0.f);
    float cnt = 0.f;
#pragma unroll 4
    for (int j = b; j < e; j++) {
        int c = o2c[nbr[j]];
        float wgt = (c >= 0) ? 1.f : 0.f;
        int idx = (c >= 0) ? c : 0;
        float4 v = ((const float4*)(X + (size_t)idx * D128))[lane];
        acc.x += wgt * v.x; acc.y += wgt * v.y;
        acc.z += wgt * v.z; acc.w += wgt * v.w;
        cnt += wgt;
    }
    float inv = 1.0f / fmaxf(cnt, 1.f);
    acc.x *= inv; acc.y *= inv; acc.z *= inv; acc.w *= inv;
    ((float4*)(mean + (size_t)w * D128))[lane] = acc;
}

// ---------------- weight pre-split for all 3 layers (one launch) ----------------
__global__ void k_splitB_all(const float* __restrict__ Wl1, const float* __restrict__ Wr1,
                             const float* __restrict__ Wl2, const float* __restrict__ Wr2,
                             const float* __restrict__ Wl3, const float* __restrict__ Wr3,
                             float* __restrict__ bh, float* __restrict__ bl) {
    int i = blockIdx.x * blockDim.x + threadIdx.x;   // 3 * 32768
    int l = i >> 15, j = i & 32767;
    const float* Wl = (l == 0) ? Wl1 : (l == 1) ? Wl2 : Wl3;
    const float* Wr = (l == 0) ? Wr1 : (l == 1) ? Wr2 : Wr3;
    float v = (j < 16384) ? Wl[j] : Wr[j - 16384];
    uint32_t hi, lo;
    tf32_split(v, hi, lo);
    bh[i] = __uint_as_float(hi);
    bl[i] = __uint_as_float(lo);
}

// ---------------- tf32 mma GEMM + fused score epilogue ----------------
// H = relu([mean|x] @ [Wl;Wr] + bl);  score = tanh(H . pw / ||pw||)
#define ACH 16
#define ASTR 20
#define BSTR 136

__global__ void __launch_bounds__(256, 2)
k_gemm_mma(const float* __restrict__ Am, const float* __restrict__ Ax,
           const float* __restrict__ Bhi, const float* __restrict__ Blo,
           const float* __restrict__ bias, const float* __restrict__ pw,
           float* __restrict__ H, float* __restrict__ score, int n) {
    __shared__ float Ah[128 * ASTR];
    __shared__ float Al[128 * ASTR];
    __shared__ float Bh[ACH * BSTR];
    __shared__ float Bl[ACH * BSTR];
    __shared__ float s_rnorm;
    int t = threadIdx.x, lane = t & 31, wid = t >> 5;
    int wm = (wid >> 2) * 64;
    int wn = (wid & 3) * 32;
    int m0 = blockIdx.x * 128;

    if (t < 32) {
        float4 w4 = ((const float4*)pw)[t];
        float nn = w4.x * w4.x + w4.y * w4.y + w4.z * w4.z + w4.w * w4.w;
#pragma unroll
        for (int off = 16; off > 0; off >>= 1)
            nn += __shfl_xor_sync(0xFFFFFFFF, nn, off);
        if (t == 0) s_rnorm = 1.0f / sqrtf(nn);
    }

    float c[4][4][4];
#pragma unroll
    for (int i = 0; i < 4; i++)
#pragma unroll
        for (int j = 0; j < 4; j++)
#pragma unroll
            for (int r = 0; r < 4; r++) c[i][j][r] = 0.f;

    int arow = t >> 1, acol0 = (t & 1) * 8;
    int brow = t >> 4, bcol0 = (t & 15) * 8;

    for (int ch = 0; ch < 16; ch++) {
        const float* A = (ch < 8) ? Am + (size_t)m0 * D128 + ch * ACH
                                  : Ax + (size_t)m0 * D128 + (ch - 8) * ACH;
#pragma unroll
        for (int q = 0; q < 2; q++) {
            float4 v = *(const float4*)(A + (size_t)arow * D128 + acol0 + q * 4);
            uint32_t h0, h1, h2, h3, l0, l1, l2, l3;
            tf32_split(v.x, h0, l0); tf32_split(v.y, h1, l1);
            tf32_split(v.z, h2, l2); tf32_split(v.w, h3, l3);
            float4 hv = make_float4(__uint_as_float(h0), __uint_as_float(h1),
                                    __uint_as_float(h2), __uint_as_float(h3));
            float4 lv = make_float4(__uint_as_float(l0), __uint_as_float(l1),
                                    __uint_as_float(l2), __uint_as_float(l3));
            *(float4*)(Ah + arow * ASTR + acol0 + q * 4) = hv;
            *(float4*)(Al + arow * ASTR + acol0 + q * 4) = lv;
        }
#pragma unroll
        for (int q = 0; q < 2; q++) {
            *(float4*)(Bh + brow * BSTR + bcol0 + q * 4) =
                *(const float4*)(Bhi + (size_t)(ch * ACH + brow) * D128 + bcol0 + q * 4);
            *(float4*)(Bl + brow * BSTR + bcol0 + q * 4) =
                *(const float4*)(Blo + (size_t)(ch * ACH + brow) * D128 + bcol0 + q * 4);
        }
        __syncthreads();

#pragma unroll
        for (int ks = 0; ks < 2; ks++) {
            uint32_t ah[4][4], bh[4][2];
#pragma unroll
            for (int mf = 0; mf < 4; mf++)
#pragma unroll
                for (int r = 0; r < 4; r++)
                    ah[mf][r] = __float_as_uint(
                        Ah[(wm + mf * 16 + (lane >> 2) + 8 * (r & 1)) * ASTR
                           + ks * 8 + (lane & 3) + 4 * (r >> 1)]);
#pragma unroll
            for (int nf = 0; nf < 4; nf++)
#pragma unroll
                for (int r = 0; r < 2; r++)
                    bh[nf][r] = __float_as_uint(
                        Bh[(ks * 8 + (lane & 3) + 4 * r) * BSTR + wn + nf * 8 + (lane >> 2)]);
#pragma unroll
            for (int mf = 0; mf < 4; mf++)
#pragma unroll
                for (int nf = 0; nf < 4; nf++)
                    mma_m16n8k8(c[mf][nf], ah[mf], bh[nf]);
            {
                uint32_t blo[4][2];
#pragma unroll
                for (int nf = 0; nf < 4; nf++)
#pragma unroll
                    for (int r = 0; r < 2; r++)
                        blo[nf][r] = __float_as_uint(
                            Bl[(ks * 8 + (lane & 3) + 4 * r) * BSTR + wn + nf * 8 + (lane >> 2)]);
#pragma unroll
                for (int mf = 0; mf < 4; mf++)
#pragma unroll
                    for (int nf = 0; nf < 4; nf++)
                        mma_m16n8k8(c[mf][nf], ah[mf], blo[nf]);
            }
            {
                uint32_t al[4][4];
#pragma unroll
                for (int mf = 0; mf < 4; mf++)
#pragma unroll
                    for (int r = 0; r < 4; r++)
                        al[mf][r] = __float_as_uint(
                            Al[(wm + mf * 16 + (lane >> 2) + 8 * (r & 1)) * ASTR
                               + ks * 8 + (lane & 3) + 4 * (r >> 1)]);
#pragma unroll
                for (int mf = 0; mf < 4; mf++)
#pragma unroll
                    for (int nf = 0; nf < 4; nf++)
                        mma_m16n8k8(c[mf][nf], al[mf], bh[nf]);
            }
        }
        __syncthreads();
    }

    // ---- epilogue: bias + relu + H store + fused score ----
    int r0 = lane >> 2, cq = (lane & 3) * 2;
    float pwv[4][2];
#pragma unroll
    for (int nf = 0; nf < 4; nf++) {
        pwv[nf][0] = pw[wn + nf * 8 + cq];
        pwv[nf][1] = pw[wn + nf * 8 + cq + 1];
    }
    float* sdot = Bh;   // reuse: [128][4]
#pragma unroll
    for (int mf = 0; mf < 4; mf++) {
        int row = m0 + wm + mf * 16 + r0;
        float p0 = 0.f, p1 = 0.f;
#pragma unroll
        for (int nf = 0; nf < 4; nf++) {
            int col = wn + nf * 8 + cq;
            float b0 = bias[col], b1 = bias[col + 1];
            float2 o0, o1;
            o0.x = fmaxf(c[mf][nf][0] + b0, 0.f);
            o0.y = fmaxf(c[mf][nf][1] + b1, 0.f);
            o1.x = fmaxf(c[mf][nf][2] + b0, 0.f);
            o1.y = fmaxf(c[mf][nf][3] + b1, 0.f);
            *(float2*)(H + (size_t)row * D128 + col) = o0;
            *(float2*)(H + (size_t)(row + 8) * D128 + col) = o1;
            p0 += o0.x * pwv[nf][0] + o0.y * pwv[nf][1];
            p1 += o1.x * pwv[nf][0] + o1.y * pwv[nf][1];
        }
        p0 += __shfl_xor_sync(0xFFFFFFFF, p0, 1);
        p0 += __shfl_xor_sync(0xFFFFFFFF, p0, 2);
        p1 += __shfl_xor_sync(0xFFFFFFFF, p1, 1);
        p1 += __shfl_xor_sync(0xFFFFFFFF, p1, 2);
        if ((lane & 3) == 0) {
            int rr = wm + mf * 16 + r0;
            sdot[rr * 4 + (wid & 3)] = p0;
            sdot[(rr + 8) * 4 + (wid & 3)] = p1;
        }
    }
    __syncthreads();
    if (t < 128) {
        float4 d4 = *(float4*)&sdot[t * 4];
        float dot = d4.x + d4.y + d4.z + d4.w;
        score[m0 + t] = tanhf(dot * s_rnorm);
    }
}

// per-graph bitonic top-K + fused pool write + readout + survival-map compose
__global__ void k_topk(const float* __restrict__ score, const float* __restrict__ H,
                       float* __restrict__ pool, int* __restrict__ newid,
                       float* __restrict__ s_out, int* __restrict__ o2c,
                       int* __restrict__ c2o, int Npg, int K, int round, int do_compose) {
    __shared__ float skey[1024];
    __shared__ int   sidx[1024];
    __shared__ float rmx[8][128];
    __shared__ float rsm[8][128];
    int g = blockIdx.x;
    int t = threadIdx.x;   // 1024 threads
    skey[t] = (t < Npg) ? score[g * Npg + t] : -INFINITY;
    sidx[t] = t;
    __syncthreads();
    for (int k = 2; k <= 1024; k <<= 1) {
        for (int j = k >> 1; j > 0; j >>= 1) {
            int ixj = t ^ j;
            if (ixj > t) {
                bool desc = ((t & k) == 0);
                float a = skey[t], b = skey[ixj];
                bool sw = desc ? (a < b) : (a > b);
                if (sw) {
                    skey[t] = b; skey[ixj] = a;
                    int tmp = sidx[t]; sidx[t] = sidx[ixj]; sidx[ixj] = tmp;
                }
            }
            __syncthreads();
        }
    }
    if (t < Npg) {
        int node = sidx[t];
        newid[g * Npg + node] = (t < K) ? (g * K + t) : -1;
    }
    __syncthreads();
    if (do_compose) {
        int o = g * NPG0 + t;
        int c = o2c[o];
        int nc = (c >= 0) ? newid[c] : -1;
        o2c[o] = nc;
        if (nc >= 0) c2o[nc] = o;
    }
    int f = t & 127, part = t >> 7;     // 8 parts x 128 features
    float mx = -INFINITY, sm = 0.f;
    for (int r = part; r < K; r += 8) {
        int node = sidx[r];
        float v = H[(size_t)(g * Npg + node) * D128 + f] * skey[r];
        pool[(size_t)(g * K + r) * D128 + f] = v;
        mx = fmaxf(mx, v);
        sm += v;
    }
    rmx[part][f] = mx; rsm[part][f] = sm;
    __syncthreads();
    if (t < 128) {
        float m2 = rmx[0][f], s2 = rsm[0][f];
#pragma unroll
        for (int p = 1; p < 8; p++) {
            m2 = fmaxf(m2, rmx[p][f]);
            s2 += rsm[p][f];
        }
        float mean = s2 / (float)K;
        if (round == 0) {
            s_out[g * 256 + f] = m2;
            s_out[g * 256 + 128 + f] = mean;
        } else {
            s_out[g * 256 + f] += m2;
            s_out[g * 256 + 128 + f] += mean;
        }
    }
}

// final MLP: 256->128->64->1 + sigmoid
__global__ void k_mlp(const float* __restrict__ s,
                      const float* __restrict__ W1, const float* __restrict__ b1,
                      const float* __restrict__ W2, const float* __restrict__ b2,
                      const float* __restrict__ W3, const float* __restrict__ b3,
                      float* __restrict__ out) {
    __shared__ float sh[256];
    __shared__ float h1[128];
    __shared__ float h2[64];
    __shared__ float red[128];
    int g = blockIdx.x, t = threadIdx.x;
    sh[t] = s[g * 256 + t];
    sh[t + 128] = s[g * 256 + 128 + t];
    __syncthreads();
    float acc = b1[t];
    for (int k = 0; k < 256; k++) acc += sh[k] * W1[k * 128 + t];
    h1[t] = fmaxf(acc, 0.f);
    __syncthreads();
    if (t < 64) {
        float a = b2[t];
        for (int k = 0; k < 128; k++) a += h1[k] * W2[k * 64 + t];
        h2[t] = fmaxf(a, 0.f);
    }
    __syncthreads();
    red[t] = (t < 64) ? h2[t] * W3[t] : 0.f;
    __syncthreads();
    for (int off = 64; off > 0; off >>= 1) {
        if (t < off) red[t] += red[t + off];
        __syncthreads();
    }
    if (t == 0) out[g] = 1.f / (1.f + expf(-(red[0] + b3[0])));
}

// ---------------- host orchestration ----------------
extern "C" void kernel_launch(void* const* d_in, const int* in_sizes, int n_in,
                              void* d_out, int out_size) {
    const float* x   = (const float*)d_in[0];
    const int*   ei  = (const int*)d_in[1];
    const int E = in_sizes[1] / 2;
    const int epg = E / BGR;

    const float* Wl1 = (const float*)d_in[2];
    const float* bl1 = (const float*)d_in[3];
    const float* Wr1 = (const float*)d_in[4];
    const float* pw1 = (const float*)d_in[5];
    const float* Wl2 = (const float*)d_in[6];
    const float* bl2 = (const float*)d_in[7];
    const float* Wr2 = (const float*)d_in[8];
    const float* pw2 = (const float*)d_in[9];
    const float* Wl3 = (const float*)d_in[10];
    const float* bl3 = (const float*)d_in[11];
    const float* Wr3 = (const float*)d_in[12];
    const float* pw3 = (const float*)d_in[13];
    const float* W1  = (const float*)d_in[14];
    const float* b1  = (const float*)d_in[15];
    const float* W2  = (const float*)d_in[16];
    const float* b2  = (const float*)d_in[17];
    const float* W3  = (const float*)d_in[18];
    const float* b3  = (const float*)d_in[19];

    float *meanP, *hP, *poolA, *poolB, *scoreP, *sP, *bhiP, *bloP;
    int *newidP, *o2cP, *c2oP, *rpP, *nbrP;
    cudaGetSymbolAddress((void**)&meanP, g_mean);
    cudaGetSymbolAddress((void**)&hP, g_h);
    cudaGetSymbolAddress((void**)&poolA, g_poolA);
    cudaGetSymbolAddress((void**)&poolB, g_poolB);
    cudaGetSymbolAddress((void**)&scoreP, g_score);
    cudaGetSymbolAddress((void**)&sP, g_s);
    cudaGetSymbolAddress((void**)&bhiP, g_bhi);
    cudaGetSymbolAddress((void**)&bloP, g_blo);
    cudaGetSymbolAddress((void**)&newidP, g_newid);
    cudaGetSymbolAddress((void**)&o2cP, g_orig2cur);
    cudaGetSymbolAddress((void**)&c2oP, g_cur2orig);
    cudaGetSymbolAddress((void**)&rpP, g_rowptr);
    cudaGetSymbolAddress((void**)&nbrP, g_nbr);

    const int TB = 256;

    // ---- one-time: CSR (one kernel) + all-layer weight split ----
    k_csr<<<BGR, 1024>>>(ei, ei + E, epg, rpP, nbrP, o2cP, c2oP);
    k_splitB_all<<<384, 256>>>(Wl1, Wr1, Wl2, Wr2, Wl3, Wr3, bhiP, bloP);

    struct LayerCfg {
        const float *xin, *bl, *pw;
        float* pool;
        int n, Npg, K, round;
    };
    LayerCfg layers[3] = {
        { x,     bl1, pw1, poolA, BGR * NPG0, NPG0, K1, 0 },
        { poolA, bl2, pw2, poolB, BGR * K1,   K1,   K2, 1 },
        { poolB, bl3, pw3, poolA, BGR * K2,   K2,   K3, 2 },
    };

    for (int L = 0; L < 3; L++) {
        LayerCfg& c = layers[L];
        int n = c.n;
        if (L == 0)
            k_aggregate1<<<(n * 32 + TB - 1) / TB, TB>>>(c.xin, rpP, nbrP, meanP, n);
        else
            k_aggregate<<<(n * 32 + TB - 1) / TB, TB>>>(c.xin, rpP, nbrP, c2oP, o2cP, meanP, n);
        k_gemm_mma<<<n / 128, 256>>>(meanP, c.xin, bhiP + L * 256 * D128,
                                     bloP + L * 256 * D128, c.bl, c.pw, hP, scoreP, n);
        k_topk<<<BGR, 1024>>>(scoreP, hP, c.pool, newidP, sP, o2cP, c2oP,
                              c.Npg, c.K, c.round, (L < 2) ? 1 : 0);
    }

    k_mlp<<<BGR, 128>>>(sP, W1, b1, W2, b2, W3, b3, (float*)d_out);
}

// round 11
// speedup vs baseline: 1.2587x; 1.0186x over previous
#include <cuda_runtime.h>
#include <math.h>
#include <stdint.h>

// ---------------- problem constants ----------------
#define D128 128
#define BGR 64
#define NPG0 1024
#define NMAX (BGR * NPG0)        // 65536
#define EMAX 1048576
#define K1 820                   // ceil(0.8*1024)
#define K2 656                   // ceil(0.8*820)
#define K3 525                   // ceil(0.8*656)

// ---------------- scratch (device globals; no allocations allowed) ----------------
__device__ float g_mean[NMAX * D128];
__device__ float g_h[NMAX * D128];
__device__ float g_poolA[BGR * K1 * D128];
__device__ float g_poolB[BGR * K2 * D128];
__device__ float g_score[NMAX];
__device__ int   g_newid[NMAX];
__device__ int   g_orig2cur[NMAX];
__device__ int   g_cur2orig[NMAX];
__device__ int   g_rowptr[NMAX + 1];
__device__ int   g_nbr[EMAX];
__device__ float g_bhi[3][256 * D128];
__device__ float g_blo[3][256 * D128];
__device__ float g_s[BGR * 256];

__device__ __forceinline__ void tf32_split(float v, uint32_t& hi, uint32_t& lo) {
    asm("cvt.rna.tf32.f32 %0, %1;" : "=r"(hi) : "f"(v));
    float r = v - __uint_as_float(hi);
    asm("cvt.rna.tf32.f32 %0, %1;" : "=r"(lo) : "f"(r));
}

__device__ __forceinline__ void mma_m16n8k8(float* c, const uint32_t* a, const uint32_t* b) {
    asm volatile(
        "mma.sync.aligned.m16n8k8.row.col.f32.tf32.tf32.f32 "
        "{%0,%1,%2,%3}, {%4,%5,%6,%7}, {%8,%9}, {%0,%1,%2,%3};"
        : "+f"(c[0]), "+f"(c[1]), "+f"(c[2]), "+f"(c[3])
        : "r"(a[0]), "r"(a[1]), "r"(a[2]), "r"(a[3]), "r"(b[0]), "r"(b[1]));
}

// ---------------- CSR build: one block per graph, all in SMEM ----------------
__global__ void __launch_bounds__(1024)
k_csr(const int* __restrict__ src, const int* __restrict__ dst, int epg,
      int* __restrict__ rowptr, int* __restrict__ nbr,
      int* __restrict__ o2c, int* __restrict__ c2o) {
    __shared__ int deg[1024];
    __shared__ int cur[1024];
    int g = blockIdx.x, t = threadIdx.x;
    int ebase = g * epg;
    int nbase = g * NPG0;

    deg[t] = 0;
    __syncthreads();
    for (int e = ebase + t; e < ebase + epg; e += 1024)
        atomicAdd(&deg[dst[e] - nbase], 1);
    __syncthreads();
    int my = deg[t];
    cur[t] = my;
    __syncthreads();
    for (int off = 1; off < 1024; off <<= 1) {
        int v = cur[t];
        if (t >= off) v += cur[t - off];
        __syncthreads();
        cur[t] = v;
        __syncthreads();
    }
    int ex = cur[t] - my;
    rowptr[nbase + t] = ebase + ex;
    o2c[nbase + t] = nbase + t;
    c2o[nbase + t] = nbase + t;
    if (g == 0 && t == 0) rowptr[NMAX] = BGR * epg;
    __syncthreads();
    cur[t] = ex;
    __syncthreads();
    for (int e = ebase + t; e < ebase + epg; e += 1024) {
        int d = dst[e] - nbase;
        int p = atomicAdd(&cur[d], 1);
        nbr[ebase + p] = src[e];
    }
}

// ---------------- mean aggregation ----------------
__global__ void k_aggregate1(const float* __restrict__ X, const int* __restrict__ rowptr,
                             const int* __restrict__ nbr, float* __restrict__ mean, int n) {
    int w = (blockIdx.x * blockDim.x + threadIdx.x) >> 5;
    int lane = threadIdx.x & 31;
    if (w >= n) return;
    int b = rowptr[w], e = rowptr[w + 1];
    float4 acc = make_float4(0.f, 0.f, 0.f, 0.f);
#pragma unroll 4
    for (int j = b; j < e; j++) {
        float4 v = ((const float4*)(X + (size_t)nbr[j] * D128))[lane];
        acc.x += v.x; acc.y += v.y; acc.z += v.z; acc.w += v.w;
    }
    int d = e - b;
    float inv = 1.0f / (float)(d > 0 ? d : 1);
    acc.x *= inv; acc.y *= inv; acc.z *= inv; acc.w *= inv;
    ((float4*)(mean + (size_t)w * D128))[lane] = acc;
}

__global__ void k_aggregate(const float* __restrict__ X, const int* __restrict__ rowptr,
                            const int* __restrict__ nbr, const int* __restrict__ c2o,
                            const int* __restrict__ o2c, float* __restrict__ mean, int n) {
    int w = (blockIdx.x * blockDim.x + threadIdx.x) >> 5;
    int lane = threadIdx.x & 31;
    if (w >= n) return;
    int o = c2o[w];
    int b = rowptr[o], e = rowptr[o + 1];
    float4 acc = make_float4(0.f, 0.f, 0.f, 0.f);
    float cnt = 0.f;
#pragma unroll 4
    for (int j = b; j < e; j++) {
        int c = o2c[nbr[j]];
        float wgt = (c >= 0) ? 1.f : 0.f;
        int idx = (c >= 0) ? c : 0;
        float4 v = ((const float4*)(X + (size_t)idx * D128))[lane];
        acc.x += wgt * v.x; acc.y += wgt * v.y;
        acc.z += wgt * v.z; acc.w += wgt * v.w;
        cnt += wgt;
    }
    float inv = 1.0f / fmaxf(cnt, 1.f);
    acc.x *= inv; acc.y *= inv; acc.z *= inv; acc.w *= inv;
    ((float4*)(mean + (size_t)w * D128))[lane] = acc;
}

// ---------------- weight pre-split for all 3 layers (one launch) ----------------
__global__ void k_splitB_all(const float* __restrict__ Wl1, const float* __restrict__ Wr1,
                             const float* __restrict__ Wl2, const float* __restrict__ Wr2,
                             const float* __restrict__ Wl3, const float* __restrict__ Wr3,
                             float* __restrict__ bh, float* __restrict__ bl) {
    int i = blockIdx.x * blockDim.x + threadIdx.x;   // 3 * 32768
    int l = i >> 15, j = i & 32767;
    const float* Wl = (l == 0) ? Wl1 : (l == 1) ? Wl2 : Wl3;
    const float* Wr = (l == 0) ? Wr1 : (l == 1) ? Wr2 : Wr3;
    float v = (j < 16384) ? Wl[j] : Wr[j - 16384];
    uint32_t hi, lo;
    tf32_split(v, hi, lo);
    bh[i] = __uint_as_float(hi);
    bl[i] = __uint_as_float(lo);
}

// ---------------- tf32 mma GEMM, double-buffered pipeline + fused score ----------------
// H = relu([mean|x] @ [Wl;Wr] + bl);  score = tanh(H . pw / ||pw||)
#define ACH 16
#define ASTR 20
#define BSTR 136
// per-buffer float offsets
#define OF_AH 0
#define OF_AL (128 * ASTR)
#define OF_BH (2 * 128 * ASTR)
#define OF_BL (2 * 128 * ASTR + ACH * BSTR)
#define PBUF  (2 * 128 * ASTR + 2 * ACH * BSTR)     // 9472 floats
#define GEMM_SMEM_BYTES (2 * PBUF * 4)              // 75776 bytes

__global__ void __launch_bounds__(256, 2)
k_gemm_mma(const float* __restrict__ Am, const float* __restrict__ Ax,
           const float* __restrict__ Bhi, const float* __restrict__ Blo,
           const float* __restrict__ bias, const float* __restrict__ pw,
           float* __restrict__ H, float* __restrict__ score, int n) {
    extern __shared__ float smem[];
    __shared__ float s_rnorm;
    int t = threadIdx.x, lane = t & 31, wid = t >> 5;
    int wm = (wid >> 2) * 64;
    int wn = (wid & 3) * 32;
    int m0 = blockIdx.x * 128;

    if (t < 32) {
        float4 w4 = ((const float4*)pw)[t];
        float nn = w4.x * w4.x + w4.y * w4.y + w4.z * w4.z + w4.w * w4.w;
#pragma unroll
        for (int off = 16; off > 0; off >>= 1)
            nn += __shfl_xor_sync(0xFFFFFFFF, nn, off);
        if (t == 0) s_rnorm = 1.0f / sqrtf(nn);
    }

    float c[4][4][4];
#pragma unroll
    for (int i = 0; i < 4; i++)
#pragma unroll
        for (int j = 0; j < 4; j++)
#pragma unroll
            for (int r = 0; r < 4; r++) c[i][j][r] = 0.f;

    int arow = t >> 1, acol0 = (t & 1) * 8;
    int brow = t >> 4, bcol0 = (t & 15) * 8;

    // staging registers
    float4 sa0, sa1, sbh0, sbh1, sbl0, sbl1;

    // prologue: load chunk 0
    {
        const float* A = Am + (size_t)(m0 + arow) * D128 + acol0;
        sa0 = *(const float4*)A;
        sa1 = *(const float4*)(A + 4);
        const float* bhp = Bhi + (size_t)brow * D128 + bcol0;
        const float* blp = Blo + (size_t)brow * D128 + bcol0;
        sbh0 = *(const float4*)bhp;  sbh1 = *(const float4*)(bhp + 4);
        sbl0 = *(const float4*)blp;  sbl1 = *(const float4*)(blp + 4);
    }
    // store chunk 0 into buffer 0
    {
        float* buf = smem;
        float av[8] = {sa0.x, sa0.y, sa0.z, sa0.w, sa1.x, sa1.y, sa1.z, sa1.w};
        float* ah = buf + OF_AH + arow * ASTR + acol0;
        float* al = buf + OF_AL + arow * ASTR + acol0;
#pragma unroll
        for (int e = 0; e < 8; e++) {
            uint32_t hi, lo;
            tf32_split(av[e], hi, lo);
            ah[e] = __uint_as_float(hi);
            al[e] = __uint_as_float(lo);
        }
        float* bh = buf + OF_BH + brow * BSTR + bcol0;
        float* bl = buf + OF_BL + brow * BSTR + bcol0;
        *(float4*)bh = sbh0; *(float4*)(bh + 4) = sbh1;
        *(float4*)bl = sbl0; *(float4*)(bl + 4) = sbl1;
    }

    for (int ch = 0; ch < 16; ch++) {
        __syncthreads();   // buf[ch&1] ready for all
        // prefetch chunk ch+1 (latency hidden by compute below)
        if (ch < 15) {
            int nc = ch + 1;
            const float* A = (nc < 8)
                ? Am + (size_t)(m0 + arow) * D128 + nc * ACH + acol0
                : Ax + (size_t)(m0 + arow) * D128 + (nc - 8) * ACH + acol0;
            sa0 = *(const float4*)A;
            sa1 = *(const float4*)(A + 4);
            const float* bhp = Bhi + (size_t)(nc * ACH + brow) * D128 + bcol0;
            const float* blp = Blo + (size_t)(nc * ACH + brow) * D128 + bcol0;
            sbh0 = *(const float4*)bhp;  sbh1 = *(const float4*)(bhp + 4);
            sbl0 = *(const float4*)blp;  sbl1 = *(const float4*)(blp + 4);
        }
        // compute on buf[ch&1]
        const float* Ahb = smem + (ch & 1) * PBUF + OF_AH;
        const float* Alb = smem + (ch & 1) * PBUF + OF_AL;
        const float* Bhb = smem + (ch & 1) * PBUF + OF_BH;
        const float* Blb = smem + (ch & 1) * PBUF + OF_BL;
#pragma unroll
        for (int ks = 0; ks < 2; ks++) {
            uint32_t ah[4][4], bh[4][2];
#pragma unroll
            for (int mf = 0; mf < 4; mf++)
#pragma unroll
                for (int r = 0; r < 4; r++)
                    ah[mf][r] = __float_as_uint(
                        Ahb[(wm + mf * 16 + (lane >> 2) + 8 * (r & 1)) * ASTR
                            + ks * 8 + (lane & 3) + 4 * (r >> 1)]);
#pragma unroll
            for (int nf = 0; nf < 4; nf++)
#pragma unroll
                for (int r = 0; r < 2; r++)
                    bh[nf][r] = __float_as_uint(
                        Bhb[(ks * 8 + (lane & 3) + 4 * r) * BSTR + wn + nf * 8 + (lane >> 2)]);
#pragma unroll
            for (int mf = 0; mf < 4; mf++)
#pragma unroll
                for (int nf = 0; nf < 4; nf++)
                    mma_m16n8k8(c[mf][nf], ah[mf], bh[nf]);
            {
                uint32_t blo[4][2];
#pragma unroll
                for (int nf = 0; nf < 4; nf++)
#pragma unroll
                    for (int r = 0; r < 2; r++)
                        blo[nf][r] = __float_as_uint(
                            Blb[(ks * 8 + (lane & 3) + 4 * r) * BSTR + wn + nf * 8 + (lane >> 2)]);
#pragma unroll
                for (int mf = 0; mf < 4; mf++)
#pragma unroll
                    for (int nf = 0; nf < 4; nf++)
                        mma_m16n8k8(c[mf][nf], ah[mf], blo[nf]);
            }
            {
                uint32_t al[4][4];
#pragma unroll
                for (int mf = 0; mf < 4; mf++)
#pragma unroll
                    for (int r = 0; r < 4; r++)
                        al[mf][r] = __float_as_uint(
                            Alb[(wm + mf * 16 + (lane >> 2) + 8 * (r & 1)) * ASTR
                                + ks * 8 + (lane & 3) + 4 * (r >> 1)]);
#pragma unroll
                for (int mf = 0; mf < 4; mf++)
#pragma unroll
                    for (int nf = 0; nf < 4; nf++)
                        mma_m16n8k8(c[mf][nf], al[mf], bh[nf]);
            }
        }
        // store prefetched chunk into the other buffer (no barrier needed: disjoint)
        if (ch < 15) {
            float* buf = smem + ((ch + 1) & 1) * PBUF;
            float av[8] = {sa0.x, sa0.y, sa0.z, sa0.w, sa1.x, sa1.y, sa1.z, sa1.w};
            float* ah = buf + OF_AH + arow * ASTR + acol0;
            float* al = buf + OF_AL + arow * ASTR + acol0;
#pragma unroll
            for (int e = 0; e < 8; e++) {
                uint32_t hi, lo;
                tf32_split(av[e], hi, lo);
                ah[e] = __uint_as_float(hi);
                al[e] = __uint_as_float(lo);
            }
            float* bh = buf + OF_BH + brow * BSTR + bcol0;
            float* bl = buf + OF_BL + brow * BSTR + bcol0;
            *(float4*)bh = sbh0; *(float4*)(bh + 4) = sbh1;
            *(float4*)bl = sbl0; *(float4*)(bl + 4) = sbl1;
        }
    }

    // ---- epilogue: bias + relu + H store + fused score ----
    // last compute read buf1; buf0 is free for sdot staging
    int r0 = lane >> 2, cq = (lane & 3) * 2;
    float pwv[4][2];
#pragma unroll
    for (int nf = 0; nf < 4; nf++) {
        pwv[nf][0] = pw[wn + nf * 8 + cq];
        pwv[nf][1] = pw[wn + nf * 8 + cq + 1];
    }
    float* sdot = smem + OF_BH;   // buffer 0 B region, 512 floats used
#pragma unroll
    for (int mf = 0; mf < 4; mf++) {
        int row = m0 + wm + mf * 16 + r0;
        float p0 = 0.f, p1 = 0.f;
#pragma unroll
        for (int nf = 0; nf < 4; nf++) {
            int col = wn + nf * 8 + cq;
            float b0 = bias[col], b1 = bias[col + 1];
            float2 o0, o1;
            o0.x = fmaxf(c[mf][nf][0] + b0, 0.f);
            o0.y = fmaxf(c[mf][nf][1] + b1, 0.f);
            o1.x = fmaxf(c[mf][nf][2] + b0, 0.f);
            o1.y = fmaxf(c[mf][nf][3] + b1, 0.f);
            *(float2*)(H + (size_t)row * D128 + col) = o0;
            *(float2*)(H + (size_t)(row + 8) * D128 + col) = o1;
            p0 += o0.x * pwv[nf][0] + o0.y * pwv[nf][1];
            p1 += o1.x * pwv[nf][0] + o1.y * pwv[nf][1];
        }
        p0 += __shfl_xor_sync(0xFFFFFFFF, p0, 1);
        p0 += __shfl_xor_sync(0xFFFFFFFF, p0, 2);
        p1 += __shfl_xor_sync(0xFFFFFFFF, p1, 1);
        p1 += __shfl_xor_sync(0xFFFFFFFF, p1, 2);
        if ((lane & 3) == 0) {
            int rr = wm + mf * 16 + r0;
            sdot[rr * 4 + (wid & 3)] = p0;
            sdot[(rr + 8) * 4 + (wid & 3)] = p1;
        }
    }
    __syncthreads();
    if (t < 128) {
        float4 d4 = *(float4*)&sdot[t * 4];
        float dot = d4.x + d4.y + d4.z + d4.w;
        score[m0 + t] = tanhf(dot * s_rnorm);
    }
}

// per-graph bitonic top-K + fused pool write + readout + survival-map compose
__global__ void k_topk(const float* __restrict__ score, const float* __restrict__ H,
                       float* __restrict__ pool, int* __restrict__ newid,
                       float* __restrict__ s_out, int* __restrict__ o2c,
                       int* __restrict__ c2o, int Npg, int K, int round, int do_compose) {
    __shared__ float skey[1024];
    __shared__ int   sidx[1024];
    __shared__ float rmx[8][128];
    __shared__ float rsm[8][128];
    int g = blockIdx.x;
    int t = threadIdx.x;   // 1024 threads
    skey[t] = (t < Npg) ? score[g * Npg + t] : -INFINITY;
    sidx[t] = t;
    __syncthreads();
    for (int k = 2; k <= 1024; k <<= 1) {
        for (int j = k >> 1; j > 0; j >>= 1) {
            int ixj = t ^ j;
            if (ixj > t) {
                bool desc = ((t & k) == 0);
                float a = skey[t], b = skey[ixj];
                bool sw = desc ? (a < b) : (a > b);
                if (sw) {
                    skey[t] = b; skey[ixj] = a;
                    int tmp = sidx[t]; sidx[t] = sidx[ixj]; sidx[ixj] = tmp;
                }
            }
            __syncthreads();
        }
    }
    if (t < Npg) {
        int node = sidx[t];
        newid[g * Npg + node] = (t < K) ? (g * K + t) : -1;
    }
    __syncthreads();
    if (do_compose) {
        int o = g * NPG0 + t;
        int c = o2c[o];
        int nc = (c >= 0) ? newid[c] : -1;
        o2c[o] = nc;
        if (nc >= 0) c2o[nc] = o;
    }
    int f = t & 127, part = t >> 7;     // 8 parts x 128 features
    float mx = -INFINITY, sm = 0.f;
    for (int r = part; r < K; r += 8) {
        int node = sidx[r];
        float v = H[(size_t)(g * Npg + node) * D128 + f] * skey[r];
        pool[(size_t)(g * K + r) * D128 + f] = v;
        mx = fmaxf(mx, v);
        sm += v;
    }
    rmx[part][f] = mx; rsm[part][f] = sm;
    __syncthreads();
    if (t < 128) {
        float m2 = rmx[0][f], s2 = rsm[0][f];
#pragma unroll
        for (int p = 1; p < 8; p++) {
            m2 = fmaxf(m2, rmx[p][f]);
            s2 += rsm[p][f];
        }
        float mean = s2 / (float)K;
        if (round == 0) {
            s_out[g * 256 + f] = m2;
            s_out[g * 256 + 128 + f] = mean;
        } else {
            s_out[g * 256 + f] += m2;
            s_out[g * 256 + 128 + f] += mean;
        }
    }
}

// final MLP: 256->128->64->1 + sigmoid
__global__ void k_mlp(const float* __restrict__ s,
                      const float* __restrict__ W1, const float* __restrict__ b1,
                      const float* __restrict__ W2, const float* __restrict__ b2,
                      const float* __restrict__ W3, const float* __restrict__ b3,
                      float* __restrict__ out) {
    __shared__ float sh[256];
    __shared__ float h1[128];
    __shared__ float h2[64];
    __shared__ float red[128];
    int g = blockIdx.x, t = threadIdx.x;
    sh[t] = s[g * 256 + t];
    sh[t + 128] = s[g * 256 + 128 + t];
    __syncthreads();
    float acc = b1[t];
    for (int k = 0; k < 256; k++) acc += sh[k] * W1[k * 128 + t];
    h1[t] = fmaxf(acc, 0.f);
    __syncthreads();
    if (t < 64) {
        float a = b2[t];
        for (int k = 0; k < 128; k++) a += h1[k] * W2[k * 64 + t];
        h2[t] = fmaxf(a, 0.f);
    }
    __syncthreads();
    red[t] = (t < 64) ? h2[t] * W3[t] : 0.f;
    __syncthreads();
    for (int off = 64; off > 0; off >>= 1) {
        if (t < off) red[t] += red[t + off];
        __syncthreads();
    }
    if (t == 0) out[g] = 1.f / (1.f + expf(-(red[0] + b3[0])));
}

// ---------------- host orchestration ----------------
extern "C" void kernel_launch(void* const* d_in, const int* in_sizes, int n_in,
                              void* d_out, int out_size) {
    const float* x   = (const float*)d_in[0];
    const int*   ei  = (const int*)d_in[1];
    const int E = in_sizes[1] / 2;
    const int epg = E / BGR;

    const float* Wl1 = (const float*)d_in[2];
    const float* bl1 = (const float*)d_in[3];
    const float* Wr1 = (const float*)d_in[4];
    const float* pw1 = (const float*)d_in[5];
    const float* Wl2 = (const float*)d_in[6];
    const float* bl2 = (const float*)d_in[7];
    const float* Wr2 = (const float*)d_in[8];
    const float* pw2 = (const float*)d_in[9];
    const float* Wl3 = (const float*)d_in[10];
    const float* bl3 = (const float*)d_in[11];
    const float* Wr3 = (const float*)d_in[12];
    const float* pw3 = (const float*)d_in[13];
    const float* W1  = (const float*)d_in[14];
    const float* b1  = (const float*)d_in[15];
    const float* W2  = (const float*)d_in[16];
    const float* b2  = (const float*)d_in[17];
    const float* W3  = (const float*)d_in[18];
    const float* b3  = (const float*)d_in[19];

    float *meanP, *hP, *poolA, *poolB, *scoreP, *sP, *bhiP, *bloP;
    int *newidP, *o2cP, *c2oP, *rpP, *nbrP;
    cudaGetSymbolAddress((void**)&meanP, g_mean);
    cudaGetSymbolAddress((void**)&hP, g_h);
    cudaGetSymbolAddress((void**)&poolA, g_poolA);
    cudaGetSymbolAddress((void**)&poolB, g_poolB);
    cudaGetSymbolAddress((void**)&scoreP, g_score);
    cudaGetSymbolAddress((void**)&sP, g_s);
    cudaGetSymbolAddress((void**)&bhiP, g_bhi);
    cudaGetSymbolAddress((void**)&bloP, g_blo);
    cudaGetSymbolAddress((void**)&newidP, g_newid);
    cudaGetSymbolAddress((void**)&o2cP, g_orig2cur);
    cudaGetSymbolAddress((void**)&c2oP, g_cur2orig);
    cudaGetSymbolAddress((void**)&rpP, g_rowptr);
    cudaGetSymbolAddress((void**)&nbrP, g_nbr);

    cudaFuncSetAttribute(k_gemm_mma, cudaFuncAttributeMaxDynamicSharedMemorySize,
                         GEMM_SMEM_BYTES);

    const int TB = 256;

    // ---- one-time: CSR (one kernel) + all-layer weight split ----
    k_csr<<<BGR, 1024>>>(ei, ei + E, epg, rpP, nbrP, o2cP, c2oP);
    k_splitB_all<<<384, 256>>>(Wl1, Wr1, Wl2, Wr2, Wl3, Wr3, bhiP, bloP);

    struct LayerCfg {
        const float *xin, *bl, *pw;
        float* pool;
        int n, Npg, K, round;
    };
    LayerCfg layers[3] = {
        { x,     bl1, pw1, poolA, BGR * NPG0, NPG0, K1, 0 },
        { poolA, bl2, pw2, poolB, BGR * K1,   K1,   K2, 1 },
        { poolB, bl3, pw3, poolA, BGR * K2,   K2,   K3, 2 },
    };

    for (int L = 0; L < 3; L++) {
        LayerCfg& c = layers[L];
        int n = c.n;
        if (L == 0)
            k_aggregate1<<<(n * 32 + TB - 1) / TB, TB>>>(c.xin, rpP, nbrP, meanP, n);
        else
            k_aggregate<<<(n * 32 + TB - 1) / TB, TB>>>(c.xin, rpP, nbrP, c2oP, o2cP, meanP, n);
        k_gemm_mma<<<n / 128, 256, GEMM_SMEM_BYTES>>>(
            meanP, c.xin, bhiP + L * 256 * D128, bloP + L * 256 * D128,
            c.bl, c.pw, hP, scoreP, n);
        k_topk<<<BGR, 1024>>>(scoreP, hP, c.pool, newidP, sP, o2cP, c2oP,
                              c.Npg, c.K, c.round, (L < 2) ? 1 : 0);
    }

    k_mlp<<<BGR, 128>>>(sP, W1, b1, W2, b2, W3, b3, (float*)d_out);
}